// round 2
// baseline (speedup 1.0000x reference)
#include <cuda_runtime.h>
#include <math.h>
#include <float.h>

// Problem constants
#define B_    4
#define NSEQ  4096
#define DIM   1024
#define H_    16
#define DH    64
#define WS    128
#define NW    32          // NSEQ / WS
#define JW    256         // (backward+forward+1) * WS
#define QKVC  3072
#define M1    (B_ * NSEQ) // 16384

// Scratch (no cudaMalloc allowed) — allocated at module load
__device__ float g_qkv[(size_t)M1 * QKVC]; // 192 MB
__device__ float g_att[(size_t)M1 * DIM];  // 64 MB

// ---------------------------------------------------------------------------
// SGEMM: C[M,N] = A[M,K] @ B[K,N], all row-major. BM=BN=128, BK=8, TM=TN=8.
// ---------------------------------------------------------------------------
#define BM 128
#define BN 128
#define BK 8
#define TM 8
#define TN 8

__global__ __launch_bounds__(256) void sgemm_kernel(
    int M, int N, int K,
    const float* __restrict__ A,
    const float* __restrict__ B,
    float* __restrict__ C)
{
    const int cRow = blockIdx.y;
    const int cCol = blockIdx.x;

    __shared__ float As[BK * BM];
    __shared__ float Bs[BK * BN];

    const int tid = threadIdx.x;
    const int threadCol = tid % (BN / TN); // 0..15
    const int threadRow = tid / (BN / TN); // 0..15

    A += (size_t)cRow * BM * K;
    B += cCol * BN;
    C += (size_t)cRow * BM * N + cCol * BN;

    const int innerRowA = tid / (BK / 4); // 0..127
    const int innerColA = tid % (BK / 4); // 0..1
    const int innerRowB = tid / (BN / 4); // 0..7
    const int innerColB = tid % (BN / 4); // 0..31

    float acc[TM * TN];
    #pragma unroll
    for (int i = 0; i < TM * TN; ++i) acc[i] = 0.0f;
    float regM[TM], regN[TN];

    for (int bk = 0; bk < K; bk += BK) {
        float4 ta = *(const float4*)&A[(size_t)innerRowA * K + innerColA * 4];
        As[(innerColA * 4 + 0) * BM + innerRowA] = ta.x;
        As[(innerColA * 4 + 1) * BM + innerRowA] = ta.y;
        As[(innerColA * 4 + 2) * BM + innerRowA] = ta.z;
        As[(innerColA * 4 + 3) * BM + innerRowA] = ta.w;
        *(float4*)&Bs[innerRowB * BN + innerColB * 4] =
            *(const float4*)&B[(size_t)innerRowB * N + innerColB * 4];
        __syncthreads();

        A += BK;
        B += (size_t)BK * N;

        #pragma unroll
        for (int k = 0; k < BK; ++k) {
            #pragma unroll
            for (int i = 0; i < TM; ++i) regM[i] = As[k * BM + threadRow * TM + i];
            #pragma unroll
            for (int j = 0; j < TN; ++j) regN[j] = Bs[k * BN + threadCol * TN + j];
            #pragma unroll
            for (int i = 0; i < TM; ++i)
                #pragma unroll
                for (int j = 0; j < TN; ++j)
                    acc[i * TN + j] += regM[i] * regN[j];
        }
        __syncthreads();
    }

    #pragma unroll
    for (int i = 0; i < TM; ++i) {
        #pragma unroll
        for (int j = 0; j < TN; j += 4) {
            float4 t;
            t.x = acc[i * TN + j + 0];
            t.y = acc[i * TN + j + 1];
            t.z = acc[i * TN + j + 2];
            t.w = acc[i * TN + j + 3];
            *(float4*)&C[(size_t)(threadRow * TM + i) * N + threadCol * TN + j] = t;
        }
    }
}

// ---------------------------------------------------------------------------
// Local attention: one block per (b, h, w). 128 threads, thread i = query i.
// smem: sK[256][64] (reused for V) + sS[128][257] score buffer.
// Valid keys for query i: j in [i, i+128], and j >= 128 when w == 0.
// RoPE positions are window-relative: q -> 128+i, k -> j.
// ---------------------------------------------------------------------------
#define SROW 257
#define ATTN_SMEM_BYTES ((JW * DH + WS * SROW) * (int)sizeof(float))

__global__ __launch_bounds__(128) void attn_kernel()
{
    extern __shared__ float smem[];
    float* sK = smem;             // [256][64]
    float* sS = smem + JW * DH;   // [128][257]

    const int blk = blockIdx.x;
    const int w = blk & (NW - 1);
    const int h = (blk >> 5) & (H_ - 1);
    const int b = blk >> 9;
    const int tid = threadIdx.x;
    const size_t base = (size_t)b * NSEQ;

    const float RC = 0.28782313662425575f; // ln(10000)/32

    // --- load K tile (window w-1 .. w), pad with 0 (masked anyway) ---
    #pragma unroll 4
    for (int it = 0; it < 32; ++it) {
        int idx4 = it * 128 + tid;
        int j  = idx4 >> 4;
        int d4 = idx4 & 15;
        int p  = w * WS - WS + j;
        float4 v = make_float4(0.f, 0.f, 0.f, 0.f);
        if (p >= 0)
            v = *(const float4*)&g_qkv[(base + p) * QKVC + DIM + h * DH + d4 * 4];
        *(float4*)&sK[j * DH + d4 * 4] = v;
    }
    __syncthreads();

    // --- RoPE K in place (position = j) ---
    for (int it = 0; it < 64; ++it) {
        int idx = it * 128 + tid;
        int j = idx >> 5;
        int m = idx & 31;
        float f = (float)j * expf(-(float)m * RC);
        float c = cosf(f), s = sinf(f);
        float k0 = sK[j * DH + m];
        float k1 = sK[j * DH + m + 32];
        sK[j * DH + m]      = k0 * c - k1 * s;
        sK[j * DH + m + 32] = k1 * c + k0 * s;
    }
    __syncthreads();

    const int i = tid;

    // --- load + scale + RoPE q (position = 128 + i) ---
    float q[DH];
    {
        const float4* qr = (const float4*)&g_qkv[(base + w * WS + i) * QKVC + h * DH];
        #pragma unroll
        for (int d4 = 0; d4 < 16; ++d4) {
            float4 v = qr[d4];
            q[d4 * 4 + 0] = v.x * 0.125f;
            q[d4 * 4 + 1] = v.y * 0.125f;
            q[d4 * 4 + 2] = v.z * 0.125f;
            q[d4 * 4 + 3] = v.w * 0.125f;
        }
        float pos = (float)(WS + i);
        #pragma unroll
        for (int m = 0; m < 32; ++m) {
            float f = pos * expf(-(float)m * RC);
            float c = cosf(f), s = sinf(f);
            float q0 = q[m], q1 = q[m + 32];
            q[m]      = q0 * c - q1 * s;
            q[m + 32] = q1 * c + q0 * s;
        }
    }

    const int jlo = (w == 0) ? WS : i;
    const int jhi = i + WS; // inclusive

    // --- scores for valid keys only ---
    for (int j = jlo; j <= jhi; ++j) {
        const float4* kr = (const float4*)&sK[j * DH];
        float a0 = 0.f, a1 = 0.f, a2 = 0.f, a3 = 0.f;
        #pragma unroll
        for (int d4 = 0; d4 < 16; ++d4) {
            float4 kv = kr[d4];
            a0 += q[d4 * 4 + 0] * kv.x;
            a1 += q[d4 * 4 + 1] * kv.y;
            a2 += q[d4 * 4 + 2] * kv.z;
            a3 += q[d4 * 4 + 3] * kv.w;
        }
        sS[i * SROW + j] = (a0 + a1) + (a2 + a3);
    }
    __syncthreads(); // all score reads of sK done before overwriting with V

    // --- load V tile over sK (no RoPE on V) ---
    #pragma unroll 4
    for (int it = 0; it < 32; ++it) {
        int idx4 = it * 128 + tid;
        int j  = idx4 >> 4;
        int d4 = idx4 & 15;
        int p  = w * WS - WS + j;
        float4 v = make_float4(0.f, 0.f, 0.f, 0.f);
        if (p >= 0)
            v = *(const float4*)&g_qkv[(base + p) * QKVC + 2 * DIM + h * DH + d4 * 4];
        *(float4*)&sK[j * DH + d4 * 4] = v;
    }

    // --- softmax over own row (no sync needed: own data only) ---
    float mmax = -FLT_MAX;
    for (int j = jlo; j <= jhi; ++j) mmax = fmaxf(mmax, sS[i * SROW + j]);
    float sum = 0.f;
    for (int j = jlo; j <= jhi; ++j) {
        float e = expf(sS[i * SROW + j] - mmax);
        sS[i * SROW + j] = e;
        sum += e;
    }
    const float inv = 1.0f / sum;
    __syncthreads(); // V visible to all

    // --- P @ V ---
    float acc[DH];
    #pragma unroll
    for (int d = 0; d < DH; ++d) acc[d] = 0.f;
    for (int j = jlo; j <= jhi; ++j) {
        float p = sS[i * SROW + j] * inv;
        const float4* vr = (const float4*)&sK[j * DH];
        #pragma unroll
        for (int d4 = 0; d4 < 16; ++d4) {
            float4 vv = vr[d4];
            acc[d4 * 4 + 0] += p * vv.x;
            acc[d4 * 4 + 1] += p * vv.y;
            acc[d4 * 4 + 2] += p * vv.z;
            acc[d4 * 4 + 3] += p * vv.w;
        }
    }

    float* orow = &g_att[(base + w * WS + i) * DIM + h * DH];
    #pragma unroll
    for (int d4 = 0; d4 < 16; ++d4)
        *(float4*)&orow[d4 * 4] =
            make_float4(acc[d4 * 4], acc[d4 * 4 + 1], acc[d4 * 4 + 2], acc[d4 * 4 + 3]);
}

// ---------------------------------------------------------------------------
extern "C" void kernel_launch(void* const* d_in, const int* in_sizes, int n_in,
                              void* d_out, int out_size)
{
    const float* x    = (const float*)d_in[0]; // [16384, 1024]
    const float* Wqkv = (const float*)d_in[1]; // [1024, 3072]
    const float* Wout = (const float*)d_in[2]; // [1024, 1024]
    float* out = (float*)d_out;                // [16384, 1024]

    float* qkv = nullptr;
    float* att = nullptr;
    cudaGetSymbolAddress((void**)&qkv, g_qkv);
    cudaGetSymbolAddress((void**)&att, g_att);

    cudaFuncSetAttribute(attn_kernel,
                         cudaFuncAttributeMaxDynamicSharedMemorySize,
                         ATTN_SMEM_BYTES);

    // 1) QKV projection
    {
        dim3 grid(QKVC / BN, M1 / BM); // (24, 128)
        sgemm_kernel<<<grid, 256>>>(M1, QKVC, DIM, x, Wqkv, qkv);
    }
    // 2) Windowed attention with RoPE
    {
        attn_kernel<<<B_ * H_ * NW, 128, ATTN_SMEM_BYTES>>>();
    }
    // 3) Output projection
    {
        dim3 grid(DIM / BN, M1 / BM); // (8, 128)
        sgemm_kernel<<<grid, 256>>>(M1, DIM, DIM, att, Wout, out);
    }
}

// round 5
// speedup vs baseline: 1.3692x; 1.3692x over previous
#include <cuda_runtime.h>
#include <cuda_bf16.h>
#include <math.h>
#include <float.h>
#include <stdint.h>

// ---------------------------------------------------------------------------
// Problem constants
// ---------------------------------------------------------------------------
#define B_    4
#define NSEQ  4096
#define DIM   1024
#define H_    16
#define DH    64
#define WS    128
#define NW    32          // NSEQ / WS
#define JW    256         // (backward+forward+1) * WS
#define QKVC  3072
#define M1    (B_ * NSEQ) // 16384

// ---------------------------------------------------------------------------
// Scratch (no cudaMalloc allowed)
// ---------------------------------------------------------------------------
__device__ float          g_qkv [(size_t)M1 * QKVC];   // 192 MB fp32 qkv
__device__ __nv_bfloat16  g_xh  [(size_t)M1 * DIM];    // x split hi
__device__ __nv_bfloat16  g_xl  [(size_t)M1 * DIM];    // x split lo
__device__ __nv_bfloat16  g_wqh [(size_t)QKVC * DIM];  // Wqkv^T hi  [3072][1024]
__device__ __nv_bfloat16  g_wql [(size_t)QKVC * DIM];
__device__ __nv_bfloat16  g_woh [(size_t)DIM * DIM];   // Wout^T hi  [1024][1024]
__device__ __nv_bfloat16  g_wol [(size_t)DIM * DIM];
__device__ __nv_bfloat16  g_ath [(size_t)M1 * DIM];    // attention out hi
__device__ __nv_bfloat16  g_atl [(size_t)M1 * DIM];    // attention out lo

// ---------------------------------------------------------------------------
// PTX helpers (sm_80-era: ldmatrix / mma.sync / cp.async — valid on sm_103 base)
// ---------------------------------------------------------------------------
__device__ __forceinline__ uint32_t smem_to_u32(const void* p) {
    uint32_t a;
    asm("{ .reg .u64 t; cvta.to.shared.u64 t, %1; cvt.u32.u64 %0, t; }"
        : "=r"(a) : "l"(p));
    return a;
}

__device__ __forceinline__ void ldsm_x4(uint32_t& r0, uint32_t& r1,
                                        uint32_t& r2, uint32_t& r3,
                                        uint32_t addr) {
    asm volatile("ldmatrix.sync.aligned.m8n8.x4.shared.b16 {%0,%1,%2,%3}, [%4];"
        : "=r"(r0), "=r"(r1), "=r"(r2), "=r"(r3) : "r"(addr));
}

__device__ __forceinline__ void mma_bf16(float* d, const uint32_t* a,
                                         uint32_t b0, uint32_t b1) {
    asm volatile(
        "mma.sync.aligned.m16n8k16.row.col.f32.bf16.bf16.f32 "
        "{%0,%1,%2,%3}, {%4,%5,%6,%7}, {%8,%9}, {%0,%1,%2,%3};"
        : "+f"(d[0]), "+f"(d[1]), "+f"(d[2]), "+f"(d[3])
        : "r"(a[0]), "r"(a[1]), "r"(a[2]), "r"(a[3]), "r"(b0), "r"(b1));
}

__device__ __forceinline__ void cp_async16(uint32_t dst, const void* src) {
    asm volatile("cp.async.cg.shared.global [%0], [%1], 16;"
        :: "r"(dst), "l"(src));
}
#define CP_COMMIT() asm volatile("cp.async.commit_group;" ::: "memory")
#define CP_WAIT(n)  asm volatile("cp.async.wait_group %0;" :: "n"(n) : "memory")

// ---------------------------------------------------------------------------
// Prep kernels: fp32 -> bf16 hi/lo split (and transposed split for weights)
// ---------------------------------------------------------------------------
__global__ __launch_bounds__(256) void split_kernel(
    const float* __restrict__ src,
    __nv_bfloat16* __restrict__ hi, __nv_bfloat16* __restrict__ lo, int n4)
{
    int i = blockIdx.x * blockDim.x + threadIdx.x;
    if (i >= n4) return;
    float4 v = ((const float4*)src)[i];
    __nv_bfloat16 h0 = __float2bfloat16(v.x);
    __nv_bfloat16 h1 = __float2bfloat16(v.y);
    __nv_bfloat16 h2 = __float2bfloat16(v.z);
    __nv_bfloat16 h3 = __float2bfloat16(v.w);
    __nv_bfloat16 l0 = __float2bfloat16(v.x - __bfloat162float(h0));
    __nv_bfloat16 l1 = __float2bfloat16(v.y - __bfloat162float(h1));
    __nv_bfloat16 l2 = __float2bfloat16(v.z - __bfloat162float(h2));
    __nv_bfloat16 l3 = __float2bfloat16(v.w - __bfloat162float(h3));
    ((__nv_bfloat162*)hi)[i * 2]     = __halves2bfloat162(h0, h1);
    ((__nv_bfloat162*)hi)[i * 2 + 1] = __halves2bfloat162(h2, h3);
    ((__nv_bfloat162*)lo)[i * 2]     = __halves2bfloat162(l0, l1);
    ((__nv_bfloat162*)lo)[i * 2 + 1] = __halves2bfloat162(l2, l3);
}

// T[n][k] = W[k][n], split into hi/lo bf16. W is [K][N] row-major.
__global__ __launch_bounds__(256) void tsplit_kernel(
    const float* __restrict__ W,
    __nv_bfloat16* __restrict__ Th, __nv_bfloat16* __restrict__ Tl,
    int K, int N)
{
    __shared__ float t[32][33];
    int x0 = blockIdx.x * 32;
    int y0 = blockIdx.y * 32;
    int tx = threadIdx.x, ty = threadIdx.y;
    #pragma unroll
    for (int r = ty; r < 32; r += 8)
        t[r][tx] = W[(size_t)(y0 + r) * N + x0 + tx];
    __syncthreads();
    #pragma unroll
    for (int r = ty; r < 32; r += 8) {
        float v = t[tx][r];                 // = W[y0+tx][x0+r]
        __nv_bfloat16 h = __float2bfloat16(v);
        __nv_bfloat16 l = __float2bfloat16(v - __bfloat162float(h));
        size_t o = (size_t)(x0 + r) * K + y0 + tx;
        Th[o] = h;
        Tl[o] = l;
    }
}

// ---------------------------------------------------------------------------
// HMMA bf16 split-precision GEMM: C[M,N] = A[M,K] * B^T  (B stored [N][K]).
// CTA tile 128x128, BK=32, 3-stage cp.async pipeline, 8 warps (2x4),
// warp tile 64x32 = 4x4 (m16n8k16) tiles, 3 MMAs per tile (AhBh+AhBl+AlBh).
// ---------------------------------------------------------------------------
#define GK_THREADS 256
#define BKC        32
#define STAGES     3
#define TILE_B     8192                  // 128 rows x 64 bytes
#define STAGE_B    (4 * TILE_B)          // Ah, Al, Bh, Bl
#define GEMM_DYN_SMEM (STAGES * STAGE_B) // 96 KB

__global__ __launch_bounds__(GK_THREADS, 1)
void gemm_tc(int K, int N,
             const __nv_bfloat16* __restrict__ Ah, const __nv_bfloat16* __restrict__ Al,
             const __nv_bfloat16* __restrict__ Bh, const __nv_bfloat16* __restrict__ Bl,
             float* __restrict__ C)
{
    extern __shared__ __align__(1024) char smem[];
    const uint32_t smemu = smem_to_u32(smem);

    const int tid  = threadIdx.x;
    const int lane = tid & 31;
    const int wid  = tid >> 5;
    const int wm   = wid & 1;   // 0..1 -> rows wm*64
    const int wn   = wid >> 1;  // 0..3 -> cols wn*32
    const int rowBase = blockIdx.y * 128;
    const int colBase = blockIdx.x * 128;

    const __nv_bfloat16* srcs[4] = {
        Ah + (size_t)rowBase * K,
        Al + (size_t)rowBase * K,
        Bh + (size_t)colBase * K,
        Bl + (size_t)colBase * K
    };

    const int NCH = K / BKC;

    // ---- stage loader: 2048 x 16B chunks / 256 threads = 8 per thread ----
    auto load_stage = [&](int st, int cc) {
        const int koff = cc * BKC;
        const uint32_t sb = smemu + st * STAGE_B;
        #pragma unroll
        for (int i = 0; i < 8; ++i) {
            int g    = i * GK_THREADS + tid;
            int tile = g >> 9;
            int idx  = g & 511;
            int r    = idx >> 2;
            int c    = idx & 3;
            uint32_t dst = sb + tile * TILE_B + r * 64
                         + ((c ^ ((r >> 1) & 3)) << 4);
            cp_async16(dst, srcs[tile] + (size_t)r * K + koff + c * 8);
        }
    };

    float acc[4][4][4];
    #pragma unroll
    for (int a = 0; a < 4; ++a)
        #pragma unroll
        for (int b = 0; b < 4; ++b)
            #pragma unroll
            for (int d = 0; d < 4; ++d) acc[a][b][d] = 0.0f;

    // prologue
    #pragma unroll
    for (int s = 0; s < STAGES - 1; ++s) {
        load_stage(s, s);
        CP_COMMIT();
    }

    const int rA = lane & 15;
    const int kq = lane >> 4; // 0/1 -> k chunk offset

    for (int c = 0; c < NCH; ++c) {
        CP_WAIT(STAGES - 2);
        __syncthreads();

        if (c + STAGES - 1 < NCH)
            load_stage((c + STAGES - 1) % STAGES, c + STAGES - 1);
        CP_COMMIT();

        const uint32_t stA = smemu + (c % STAGES) * STAGE_B;           // Ah
        const uint32_t stB = stA + 2 * TILE_B;                          // Bh

        #pragma unroll
        for (int ks = 0; ks < 2; ++ks) {
            uint32_t ah[4][4], al[4][4], bh[2][4], bl[2][4];
            #pragma unroll
            for (int mt = 0; mt < 4; ++mt) {
                int row = wm * 64 + mt * 16 + rA;
                uint32_t addr = stA + row * 64
                              + (((ks * 2 + kq) ^ ((row >> 1) & 3)) << 4);
                ldsm_x4(ah[mt][0], ah[mt][1], ah[mt][2], ah[mt][3], addr);
                ldsm_x4(al[mt][0], al[mt][1], al[mt][2], al[mt][3], addr + TILE_B);
            }
            #pragma unroll
            for (int t = 0; t < 2; ++t) {
                int row = wn * 32 + t * 16 + rA;
                uint32_t addr = stB + row * 64
                              + (((ks * 2 + kq) ^ ((row >> 1) & 3)) << 4);
                ldsm_x4(bh[t][0], bh[t][1], bh[t][2], bh[t][3], addr);
                ldsm_x4(bl[t][0], bl[t][1], bl[t][2], bl[t][3], addr + TILE_B);
            }
            #pragma unroll
            for (int mt = 0; mt < 4; ++mt) {
                #pragma unroll
                for (int t = 0; t < 2; ++t) {
                    // n-tile 2t   : B regs {r0, r2}
                    mma_bf16(acc[mt][2 * t],     ah[mt], bh[t][0], bh[t][2]);
                    mma_bf16(acc[mt][2 * t],     ah[mt], bl[t][0], bl[t][2]);
                    mma_bf16(acc[mt][2 * t],     al[mt], bh[t][0], bh[t][2]);
                    // n-tile 2t+1 : B regs {r1, r3}
                    mma_bf16(acc[mt][2 * t + 1], ah[mt], bh[t][1], bh[t][3]);
                    mma_bf16(acc[mt][2 * t + 1], ah[mt], bl[t][1], bl[t][3]);
                    mma_bf16(acc[mt][2 * t + 1], al[mt], bh[t][1], bh[t][3]);
                }
            }
        }
        __syncthreads();
    }

    // ---- epilogue: fragment layout d0,d1 @ (row, col..col+1); d2,d3 @ row+8
    #pragma unroll
    for (int mt = 0; mt < 4; ++mt) {
        int row0 = rowBase + wm * 64 + mt * 16 + (lane >> 2);
        #pragma unroll
        for (int nt = 0; nt < 4; ++nt) {
            int col = colBase + wn * 32 + nt * 8 + (lane & 3) * 2;
            *(float2*)&C[(size_t)row0 * N + col] =
                make_float2(acc[mt][nt][0], acc[mt][nt][1]);
            *(float2*)&C[(size_t)(row0 + 8) * N + col] =
                make_float2(acc[mt][nt][2], acc[mt][nt][3]);
        }
    }
}

// ---------------------------------------------------------------------------
// Local attention (one block per (b, h, w)); outputs bf16 hi/lo for GEMM2.
// ---------------------------------------------------------------------------
#define SROW 257
#define ATTN_SMEM_BYTES ((JW * DH + WS * SROW) * (int)sizeof(float))

__global__ __launch_bounds__(128) void attn_kernel()
{
    extern __shared__ float asmem[];
    float* sK = asmem;             // [256][64]
    float* sS = asmem + JW * DH;   // [128][257]

    const int blk = blockIdx.x;
    const int w = blk & (NW - 1);
    const int h = (blk >> 5) & (H_ - 1);
    const int b = blk >> 9;
    const int tid = threadIdx.x;
    const size_t base = (size_t)b * NSEQ;

    const float RC = 0.28782313662425575f; // ln(10000)/32

    // K tile (windows w-1 .. w)
    #pragma unroll 4
    for (int it = 0; it < 32; ++it) {
        int idx4 = it * 128 + tid;
        int j  = idx4 >> 4;
        int d4 = idx4 & 15;
        int p  = w * WS - WS + j;
        float4 v = make_float4(0.f, 0.f, 0.f, 0.f);
        if (p >= 0)
            v = *(const float4*)&g_qkv[(base + p) * QKVC + DIM + h * DH + d4 * 4];
        *(float4*)&sK[j * DH + d4 * 4] = v;
    }
    __syncthreads();

    // RoPE K (pos = j)
    for (int it = 0; it < 64; ++it) {
        int idx = it * 128 + tid;
        int j = idx >> 5;
        int m = idx & 31;
        float f = (float)j * expf(-(float)m * RC);
        float c = cosf(f), s = sinf(f);
        float k0 = sK[j * DH + m];
        float k1 = sK[j * DH + m + 32];
        sK[j * DH + m]      = k0 * c - k1 * s;
        sK[j * DH + m + 32] = k1 * c + k0 * s;
    }
    __syncthreads();

    const int i = tid;

    // q load + scale + RoPE (pos = 128 + i)
    float q[DH];
    {
        const float4* qr = (const float4*)&g_qkv[(base + w * WS + i) * QKVC + h * DH];
        #pragma unroll
        for (int d4 = 0; d4 < 16; ++d4) {
            float4 v = qr[d4];
            q[d4 * 4 + 0] = v.x * 0.125f;
            q[d4 * 4 + 1] = v.y * 0.125f;
            q[d4 * 4 + 2] = v.z * 0.125f;
            q[d4 * 4 + 3] = v.w * 0.125f;
        }
        float pos = (float)(WS + i);
        #pragma unroll
        for (int m = 0; m < 32; ++m) {
            float f = pos * expf(-(float)m * RC);
            float c = cosf(f), s = sinf(f);
            float q0 = q[m], q1 = q[m + 32];
            q[m]      = q0 * c - q1 * s;
            q[m + 32] = q1 * c + q0 * s;
        }
    }

    const int jlo = (w == 0) ? WS : i;
    const int jhi = i + WS;

    for (int j = jlo; j <= jhi; ++j) {
        const float4* kr = (const float4*)&sK[j * DH];
        float a0 = 0.f, a1 = 0.f, a2 = 0.f, a3 = 0.f;
        #pragma unroll
        for (int d4 = 0; d4 < 16; ++d4) {
            float4 kv = kr[d4];
            a0 += q[d4 * 4 + 0] * kv.x;
            a1 += q[d4 * 4 + 1] * kv.y;
            a2 += q[d4 * 4 + 2] * kv.z;
            a3 += q[d4 * 4 + 3] * kv.w;
        }
        sS[i * SROW + j] = (a0 + a1) + (a2 + a3);
    }
    __syncthreads();

    // V tile over sK
    #pragma unroll 4
    for (int it = 0; it < 32; ++it) {
        int idx4 = it * 128 + tid;
        int j  = idx4 >> 4;
        int d4 = idx4 & 15;
        int p  = w * WS - WS + j;
        float4 v = make_float4(0.f, 0.f, 0.f, 0.f);
        if (p >= 0)
            v = *(const float4*)&g_qkv[(base + p) * QKVC + 2 * DIM + h * DH + d4 * 4];
        *(float4*)&sK[j * DH + d4 * 4] = v;
    }

    // softmax (own row only)
    float mmax = -FLT_MAX;
    for (int j = jlo; j <= jhi; ++j) mmax = fmaxf(mmax, sS[i * SROW + j]);
    float sum = 0.f;
    for (int j = jlo; j <= jhi; ++j) {
        float e = expf(sS[i * SROW + j] - mmax);
        sS[i * SROW + j] = e;
        sum += e;
    }
    const float inv = 1.0f / sum;
    __syncthreads();

    // P @ V
    float acc[DH];
    #pragma unroll
    for (int d = 0; d < DH; ++d) acc[d] = 0.f;
    for (int j = jlo; j <= jhi; ++j) {
        float p = sS[i * SROW + j] * inv;
        const float4* vr = (const float4*)&sK[j * DH];
        #pragma unroll
        for (int d4 = 0; d4 < 16; ++d4) {
            float4 vv = vr[d4];
            acc[d4 * 4 + 0] += p * vv.x;
            acc[d4 * 4 + 1] += p * vv.y;
            acc[d4 * 4 + 2] += p * vv.z;
            acc[d4 * 4 + 3] += p * vv.w;
        }
    }

    // write bf16 hi/lo for GEMM2
    __nv_bfloat162* oh = (__nv_bfloat162*)&g_ath[(base + w * WS + i) * DIM + h * DH];
    __nv_bfloat162* ol = (__nv_bfloat162*)&g_atl[(base + w * WS + i) * DIM + h * DH];
    #pragma unroll
    for (int d2 = 0; d2 < 32; ++d2) {
        float v0 = acc[d2 * 2], v1 = acc[d2 * 2 + 1];
        __nv_bfloat16 h0 = __float2bfloat16(v0);
        __nv_bfloat16 h1 = __float2bfloat16(v1);
        __nv_bfloat16 l0 = __float2bfloat16(v0 - __bfloat162float(h0));
        __nv_bfloat16 l1 = __float2bfloat16(v1 - __bfloat162float(h1));
        oh[d2] = __halves2bfloat162(h0, h1);
        ol[d2] = __halves2bfloat162(l0, l1);
    }
}

// ---------------------------------------------------------------------------
extern "C" void kernel_launch(void* const* d_in, const int* in_sizes, int n_in,
                              void* d_out, int out_size)
{
    const float* x    = (const float*)d_in[0]; // [16384, 1024]
    const float* Wqkv = (const float*)d_in[1]; // [1024, 3072]
    const float* Wout = (const float*)d_in[2]; // [1024, 1024]
    float* out = (float*)d_out;                // [16384, 1024]

    float *qkv;
    __nv_bfloat16 *xh, *xl, *wqh, *wql, *woh, *wol, *ath, *atl;
    cudaGetSymbolAddress((void**)&qkv, g_qkv);
    cudaGetSymbolAddress((void**)&xh,  g_xh);
    cudaGetSymbolAddress((void**)&xl,  g_xl);
    cudaGetSymbolAddress((void**)&wqh, g_wqh);
    cudaGetSymbolAddress((void**)&wql, g_wql);
    cudaGetSymbolAddress((void**)&woh, g_woh);
    cudaGetSymbolAddress((void**)&wol, g_wol);
    cudaGetSymbolAddress((void**)&ath, g_ath);
    cudaGetSymbolAddress((void**)&atl, g_atl);

    cudaFuncSetAttribute(gemm_tc, cudaFuncAttributeMaxDynamicSharedMemorySize,
                         GEMM_DYN_SMEM);
    cudaFuncSetAttribute(attn_kernel, cudaFuncAttributeMaxDynamicSharedMemorySize,
                         ATTN_SMEM_BYTES);

    // 0) split x, transpose+split weights
    {
        int n4 = (M1 * DIM) / 4;
        split_kernel<<<(n4 + 255) / 256, 256>>>(x, xh, xl, n4);
        dim3 tb(32, 8);
        tsplit_kernel<<<dim3(QKVC / 32, DIM / 32), tb>>>(Wqkv, wqh, wql, DIM, QKVC);
        tsplit_kernel<<<dim3(DIM  / 32, DIM / 32), tb>>>(Wout, woh, wol, DIM, DIM);
    }
    // 1) QKV projection: [16384,1024] x [1024,3072]
    gemm_tc<<<dim3(QKVC / 128, M1 / 128), GK_THREADS, GEMM_DYN_SMEM>>>(
        DIM, QKVC, xh, xl, wqh, wql, qkv);
    // 2) windowed attention with RoPE
    attn_kernel<<<B_ * H_ * NW, 128, ATTN_SMEM_BYTES>>>();
    // 3) output projection: [16384,1024] x [1024,1024]
    gemm_tc<<<dim3(DIM / 128, M1 / 128), GK_THREADS, GEMM_DYN_SMEM>>>(
        DIM, DIM, ath, atl, woh, wol, out);
}

// round 10
// speedup vs baseline: 3.2408x; 2.3670x over previous
#include <cuda_runtime.h>
#include <cuda_bf16.h>
#include <math.h>
#include <float.h>
#include <stdint.h>

// ---------------------------------------------------------------------------
// Problem constants
// ---------------------------------------------------------------------------
#define B_    4
#define NSEQ  4096
#define DIM   1024
#define H_    16
#define DH    64
#define WS    128
#define NW    32          // NSEQ / WS
#define JW    256         // (backward+forward+1) * WS
#define QKVC  3072
#define M1    (B_ * NSEQ) // 16384

// ---------------------------------------------------------------------------
// Scratch (no cudaMalloc allowed)
// ---------------------------------------------------------------------------
__device__ float          g_qkv [(size_t)M1 * QKVC];   // 192 MB fp32 qkv
__device__ __nv_bfloat16  g_xh  [(size_t)M1 * DIM];    // x split hi
__device__ __nv_bfloat16  g_xl  [(size_t)M1 * DIM];    // x split lo
__device__ __nv_bfloat16  g_wqh [(size_t)QKVC * DIM];  // Wqkv^T hi  [3072][1024]
__device__ __nv_bfloat16  g_wql [(size_t)QKVC * DIM];
__device__ __nv_bfloat16  g_woh [(size_t)DIM * DIM];   // Wout^T hi  [1024][1024]
__device__ __nv_bfloat16  g_wol [(size_t)DIM * DIM];
__device__ __nv_bfloat16  g_ath [(size_t)M1 * DIM];    // attention out hi
__device__ __nv_bfloat16  g_atl [(size_t)M1 * DIM];    // attention out lo

// ---------------------------------------------------------------------------
// PTX helpers (sm_80-era: ldmatrix / mma.sync / cp.async — valid on sm_103 base)
// ---------------------------------------------------------------------------
__device__ __forceinline__ uint32_t smem_to_u32(const void* p) {
    uint32_t a;
    asm("{ .reg .u64 t; cvta.to.shared.u64 t, %1; cvt.u32.u64 %0, t; }"
        : "=r"(a) : "l"(p));
    return a;
}

__device__ __forceinline__ void ldsm_x4(uint32_t& r0, uint32_t& r1,
                                        uint32_t& r2, uint32_t& r3,
                                        uint32_t addr) {
    asm volatile("ldmatrix.sync.aligned.m8n8.x4.shared.b16 {%0,%1,%2,%3}, [%4];"
        : "=r"(r0), "=r"(r1), "=r"(r2), "=r"(r3) : "r"(addr));
}

__device__ __forceinline__ void mma_bf16(float* d, const uint32_t* a,
                                         uint32_t b0, uint32_t b1) {
    asm volatile(
        "mma.sync.aligned.m16n8k16.row.col.f32.bf16.bf16.f32 "
        "{%0,%1,%2,%3}, {%4,%5,%6,%7}, {%8,%9}, {%0,%1,%2,%3};"
        : "+f"(d[0]), "+f"(d[1]), "+f"(d[2]), "+f"(d[3])
        : "r"(a[0]), "r"(a[1]), "r"(a[2]), "r"(a[3]), "r"(b0), "r"(b1));
}

__device__ __forceinline__ void cp_async16(uint32_t dst, const void* src) {
    asm volatile("cp.async.cg.shared.global [%0], [%1], 16;"
        :: "r"(dst), "l"(src));
}
#define CP_COMMIT() asm volatile("cp.async.commit_group;" ::: "memory")
#define CP_WAIT(n)  asm volatile("cp.async.wait_group %0;" :: "n"(n) : "memory")

// ---------------------------------------------------------------------------
// Prep kernels: fp32 -> bf16 hi/lo split (and transposed split for weights)
// ---------------------------------------------------------------------------
__global__ __launch_bounds__(256) void split_kernel(
    const float* __restrict__ src,
    __nv_bfloat16* __restrict__ hi, __nv_bfloat16* __restrict__ lo, int n4)
{
    int i = blockIdx.x * blockDim.x + threadIdx.x;
    if (i >= n4) return;
    float4 v = ((const float4*)src)[i];
    __nv_bfloat16 h0 = __float2bfloat16(v.x);
    __nv_bfloat16 h1 = __float2bfloat16(v.y);
    __nv_bfloat16 h2 = __float2bfloat16(v.z);
    __nv_bfloat16 h3 = __float2bfloat16(v.w);
    __nv_bfloat16 l0 = __float2bfloat16(v.x - __bfloat162float(h0));
    __nv_bfloat16 l1 = __float2bfloat16(v.y - __bfloat162float(h1));
    __nv_bfloat16 l2 = __float2bfloat16(v.z - __bfloat162float(h2));
    __nv_bfloat16 l3 = __float2bfloat16(v.w - __bfloat162float(h3));
    ((__nv_bfloat162*)hi)[i * 2]     = __halves2bfloat162(h0, h1);
    ((__nv_bfloat162*)hi)[i * 2 + 1] = __halves2bfloat162(h2, h3);
    ((__nv_bfloat162*)lo)[i * 2]     = __halves2bfloat162(l0, l1);
    ((__nv_bfloat162*)lo)[i * 2 + 1] = __halves2bfloat162(l2, l3);
}

// T[n][k] = W[k][n], split into hi/lo bf16. W is [K][N] row-major.
__global__ __launch_bounds__(256) void tsplit_kernel(
    const float* __restrict__ W,
    __nv_bfloat16* __restrict__ Th, __nv_bfloat16* __restrict__ Tl,
    int K, int N)
{
    __shared__ float t[32][33];
    int x0 = blockIdx.x * 32;
    int y0 = blockIdx.y * 32;
    int tx = threadIdx.x, ty = threadIdx.y;
    #pragma unroll
    for (int r = ty; r < 32; r += 8)
        t[r][tx] = W[(size_t)(y0 + r) * N + x0 + tx];
    __syncthreads();
    #pragma unroll
    for (int r = ty; r < 32; r += 8) {
        float v = t[tx][r];                 // = W[y0+tx][x0+r]
        __nv_bfloat16 h = __float2bfloat16(v);
        __nv_bfloat16 l = __float2bfloat16(v - __bfloat162float(h));
        size_t o = (size_t)(x0 + r) * K + y0 + tx;
        Th[o] = h;
        Tl[o] = l;
    }
}

// ---------------------------------------------------------------------------
// HMMA bf16 split-precision GEMM: C[M,N] = A[M,K] * B^T  (B stored [N][K]).
// CTA tile 128x128, BK=32, 3-stage cp.async pipeline, 8 warps (2x4),
// warp tile 64x32 = 4x4 (m16n8k16) tiles, 3 MMAs per tile (AhBh+AhBl+AlBh).
// ---------------------------------------------------------------------------
#define GK_THREADS 256
#define BKC        32
#define STAGES     3
#define TILE_B     8192                  // 128 rows x 64 bytes
#define STAGE_B    (4 * TILE_B)          // Ah, Al, Bh, Bl
#define GEMM_DYN_SMEM (STAGES * STAGE_B) // 96 KB

__global__ __launch_bounds__(GK_THREADS, 1)
void gemm_tc(int K, int N,
             const __nv_bfloat16* __restrict__ Ah, const __nv_bfloat16* __restrict__ Al,
             const __nv_bfloat16* __restrict__ Bh, const __nv_bfloat16* __restrict__ Bl,
             float* __restrict__ C)
{
    extern __shared__ __align__(1024) char smem[];
    const uint32_t smemu = smem_to_u32(smem);

    const int tid  = threadIdx.x;
    const int lane = tid & 31;
    const int wid  = tid >> 5;
    const int wm   = wid & 1;   // 0..1 -> rows wm*64
    const int wn   = wid >> 1;  // 0..3 -> cols wn*32
    const int rowBase = blockIdx.y * 128;
    const int colBase = blockIdx.x * 128;

    const int NCH = K / BKC;

    // ---- precompute per-thread cp.async src pointers & dst offsets --------
    // 2048 16B chunks / 256 threads = 8 per thread
    const __nv_bfloat16* srcp[8];
    uint32_t dsto[8];
    {
        const __nv_bfloat16* bases[4] = {
            Ah + (size_t)rowBase * K,
            Al + (size_t)rowBase * K,
            Bh + (size_t)colBase * K,
            Bl + (size_t)colBase * K
        };
        #pragma unroll
        for (int i = 0; i < 8; ++i) {
            int g    = i * GK_THREADS + tid;
            int tile = g >> 9;
            int idx  = g & 511;
            int r    = idx >> 2;
            int c    = idx & 3;
            srcp[i]  = bases[tile] + (size_t)r * K + c * 8;
            dsto[i]  = tile * TILE_B + r * 64 + ((c ^ ((r >> 1) & 3)) << 4);
        }
    }

    auto load_stage = [&](int st) {
        const uint32_t sb = smemu + st * STAGE_B;
        #pragma unroll
        for (int i = 0; i < 8; ++i) {
            cp_async16(sb + dsto[i], srcp[i]);
            srcp[i] += BKC;
        }
    };

    float acc[4][4][4];
    #pragma unroll
    for (int a = 0; a < 4; ++a)
        #pragma unroll
        for (int b = 0; b < 4; ++b)
            #pragma unroll
            for (int d = 0; d < 4; ++d) acc[a][b][d] = 0.0f;

    // prologue
    #pragma unroll
    for (int s = 0; s < STAGES - 1; ++s) {
        load_stage(s);
        CP_COMMIT();
    }

    const int rA = lane & 15;
    const int kq = lane >> 4; // 0/1 -> k chunk offset

    for (int c = 0; c < NCH; ++c) {
        CP_WAIT(STAGES - 2);
        __syncthreads();

        if (c + STAGES - 1 < NCH)
            load_stage((c + STAGES - 1) % STAGES);
        CP_COMMIT();

        const uint32_t stA = smemu + (c % STAGES) * STAGE_B;           // Ah
        const uint32_t stB = stA + 2 * TILE_B;                          // Bh

        #pragma unroll
        for (int ks = 0; ks < 2; ++ks) {
            uint32_t ah[4][4], al[4][4], bh[2][4], bl[2][4];
            #pragma unroll
            for (int mt = 0; mt < 4; ++mt) {
                int row = wm * 64 + mt * 16 + rA;
                uint32_t addr = stA + row * 64
                              + (((ks * 2 + kq) ^ ((row >> 1) & 3)) << 4);
                ldsm_x4(ah[mt][0], ah[mt][1], ah[mt][2], ah[mt][3], addr);
                ldsm_x4(al[mt][0], al[mt][1], al[mt][2], al[mt][3], addr + TILE_B);
            }
            #pragma unroll
            for (int t = 0; t < 2; ++t) {
                int row = wn * 32 + t * 16 + rA;
                uint32_t addr = stB + row * 64
                              + (((ks * 2 + kq) ^ ((row >> 1) & 3)) << 4);
                ldsm_x4(bh[t][0], bh[t][1], bh[t][2], bh[t][3], addr);
                ldsm_x4(bl[t][0], bl[t][1], bl[t][2], bl[t][3], addr + TILE_B);
            }
            #pragma unroll
            for (int mt = 0; mt < 4; ++mt) {
                #pragma unroll
                for (int t = 0; t < 2; ++t) {
                    mma_bf16(acc[mt][2 * t],     ah[mt], bh[t][0], bh[t][2]);
                    mma_bf16(acc[mt][2 * t],     ah[mt], bl[t][0], bl[t][2]);
                    mma_bf16(acc[mt][2 * t],     al[mt], bh[t][0], bh[t][2]);
                    mma_bf16(acc[mt][2 * t + 1], ah[mt], bh[t][1], bh[t][3]);
                    mma_bf16(acc[mt][2 * t + 1], ah[mt], bl[t][1], bl[t][3]);
                    mma_bf16(acc[mt][2 * t + 1], al[mt], bh[t][1], bh[t][3]);
                }
            }
        }
        // NOTE: no trailing __syncthreads needed — the top-of-loop barrier in
        // iteration c+1 orders this iteration's smem reads before the loader
        // overwrites stage (c+3)%3 == c%3.
    }

    // ---- epilogue: fragment layout d0,d1 @ (row, col..col+1); d2,d3 @ row+8
    #pragma unroll
    for (int mt = 0; mt < 4; ++mt) {
        int row0 = rowBase + wm * 64 + mt * 16 + (lane >> 2);
        #pragma unroll
        for (int nt = 0; nt < 4; ++nt) {
            int col = colBase + wn * 32 + nt * 8 + (lane & 3) * 2;
            *(float2*)&C[(size_t)row0 * N + col] =
                make_float2(acc[mt][nt][0], acc[mt][nt][1]);
            *(float2*)&C[(size_t)(row0 + 8) * N + col] =
                make_float2(acc[mt][nt][2], acc[mt][nt][3]);
        }
    }
}

// ---------------------------------------------------------------------------
// Local attention (one block per (b, h, w)); outputs bf16 hi/lo for GEMM2.
// sK rows padded to 68 floats (272 B) so lane-consecutive j accesses are
// bank-conflict-free (4*i mod 32 distinct per 8-lane phase).
// ---------------------------------------------------------------------------
#define KP   68
#define SROW 257
#define ATTN_SMEM_BYTES ((JW * KP + WS * SROW) * (int)sizeof(float))

__global__ __launch_bounds__(128) void attn_kernel()
{
    extern __shared__ float asmem[];
    float* sK = asmem;             // [256][68]
    float* sS = asmem + JW * KP;   // [128][257]

    const int blk = blockIdx.x;
    const int w = blk & (NW - 1);
    const int h = (blk >> 5) & (H_ - 1);
    const int b = blk >> 9;
    const int tid = threadIdx.x;
    const size_t base = (size_t)b * NSEQ;

    const float RC = 0.28782313662425575f; // ln(10000)/32

    // K tile (windows w-1 .. w)
    #pragma unroll 4
    for (int it = 0; it < 32; ++it) {
        int idx4 = it * 128 + tid;
        int j  = idx4 >> 4;
        int d4 = idx4 & 15;
        int p  = w * WS - WS + j;
        float4 v = make_float4(0.f, 0.f, 0.f, 0.f);
        if (p >= 0)
            v = *(const float4*)&g_qkv[(base + p) * QKVC + DIM + h * DH + d4 * 4];
        *(float4*)&sK[j * KP + d4 * 4] = v;
    }
    __syncthreads();

    // RoPE K (pos = j)
    for (int it = 0; it < 64; ++it) {
        int idx = it * 128 + tid;
        int j = idx >> 5;
        int m = idx & 31;
        float f = (float)j * expf(-(float)m * RC);
        float c = cosf(f), s = sinf(f);
        float k0 = sK[j * KP + m];
        float k1 = sK[j * KP + m + 32];
        sK[j * KP + m]      = k0 * c - k1 * s;
        sK[j * KP + m + 32] = k1 * c + k0 * s;
    }
    __syncthreads();

    const int i = tid;

    // q load + scale + RoPE (pos = 128 + i)
    float q[DH];
    {
        const float4* qr = (const float4*)&g_qkv[(base + w * WS + i) * QKVC + h * DH];
        #pragma unroll
        for (int d4 = 0; d4 < 16; ++d4) {
            float4 v = qr[d4];
            q[d4 * 4 + 0] = v.x * 0.125f;
            q[d4 * 4 + 1] = v.y * 0.125f;
            q[d4 * 4 + 2] = v.z * 0.125f;
            q[d4 * 4 + 3] = v.w * 0.125f;
        }
        float pos = (float)(WS + i);
        #pragma unroll
        for (int m = 0; m < 32; ++m) {
            float f = pos * expf(-(float)m * RC);
            float c = cosf(f), s = sinf(f);
            float q0 = q[m], q1 = q[m + 32];
            q[m]      = q0 * c - q1 * s;
            q[m + 32] = q1 * c + q0 * s;
        }
    }

    const int jlo = (w == 0) ? WS : i;
    const int jhi = i + WS;

    for (int j = jlo; j <= jhi; ++j) {
        const float4* kr = (const float4*)&sK[j * KP];
        float a0 = 0.f, a1 = 0.f, a2 = 0.f, a3 = 0.f;
        #pragma unroll
        for (int d4 = 0; d4 < 16; ++d4) {
            float4 kv = kr[d4];
            a0 += q[d4 * 4 + 0] * kv.x;
            a1 += q[d4 * 4 + 1] * kv.y;
            a2 += q[d4 * 4 + 2] * kv.z;
            a3 += q[d4 * 4 + 3] * kv.w;
        }
        sS[i * SROW + j] = (a0 + a1) + (a2 + a3);
    }
    __syncthreads();

    // V tile over sK
    #pragma unroll 4
    for (int it = 0; it < 32; ++it) {
        int idx4 = it * 128 + tid;
        int j  = idx4 >> 4;
        int d4 = idx4 & 15;
        int p  = w * WS - WS + j;
        float4 v = make_float4(0.f, 0.f, 0.f, 0.f);
        if (p >= 0)
            v = *(const float4*)&g_qkv[(base + p) * QKVC + 2 * DIM + h * DH + d4 * 4];
        *(float4*)&sK[j * KP + d4 * 4] = v;
    }

    // softmax (own row only)
    float mmax = -FLT_MAX;
    for (int j = jlo; j <= jhi; ++j) mmax = fmaxf(mmax, sS[i * SROW + j]);
    float sum = 0.f;
    for (int j = jlo; j <= jhi; ++j) {
        float e = expf(sS[i * SROW + j] - mmax);
        sS[i * SROW + j] = e;
        sum += e;
    }
    const float inv = 1.0f / sum;
    __syncthreads();

    // P @ V
    float acc[DH];
    #pragma unroll
    for (int d = 0; d < DH; ++d) acc[d] = 0.f;
    for (int j = jlo; j <= jhi; ++j) {
        float p = sS[i * SROW + j] * inv;
        const float4* vr = (const float4*)&sK[j * KP];
        #pragma unroll
        for (int d4 = 0; d4 < 16; ++d4) {
            float4 vv = vr[d4];
            acc[d4 * 4 + 0] += p * vv.x;
            acc[d4 * 4 + 1] += p * vv.y;
            acc[d4 * 4 + 2] += p * vv.z;
            acc[d4 * 4 + 3] += p * vv.w;
        }
    }

    // write bf16 hi/lo for GEMM2
    __nv_bfloat162* oh = (__nv_bfloat162*)&g_ath[(base + w * WS + i) * DIM + h * DH];
    __nv_bfloat162* ol = (__nv_bfloat162*)&g_atl[(base + w * WS + i) * DIM + h * DH];
    #pragma unroll
    for (int d2 = 0; d2 < 32; ++d2) {
        float v0 = acc[d2 * 2], v1 = acc[d2 * 2 + 1];
        __nv_bfloat16 h0 = __float2bfloat16(v0);
        __nv_bfloat16 h1 = __float2bfloat16(v1);
        __nv_bfloat16 l0 = __float2bfloat16(v0 - __bfloat162float(h0));
        __nv_bfloat16 l1 = __float2bfloat16(v1 - __bfloat162float(h1));
        oh[d2] = __halves2bfloat162(h0, h1);
        ol[d2] = __halves2bfloat162(l0, l1);
    }
}

// ---------------------------------------------------------------------------
extern "C" void kernel_launch(void* const* d_in, const int* in_sizes, int n_in,
                              void* d_out, int out_size)
{
    const float* x    = (const float*)d_in[0]; // [16384, 1024]
    const float* Wqkv = (const float*)d_in[1]; // [1024, 3072]
    const float* Wout = (const float*)d_in[2]; // [1024, 1024]
    float* out = (float*)d_out;                // [16384, 1024]

    float *qkv;
    __nv_bfloat16 *xh, *xl, *wqh, *wql, *woh, *wol, *ath, *atl;
    cudaGetSymbolAddress((void**)&qkv, g_qkv);
    cudaGetSymbolAddress((void**)&xh,  g_xh);
    cudaGetSymbolAddress((void**)&xl,  g_xl);
    cudaGetSymbolAddress((void**)&wqh, g_wqh);
    cudaGetSymbolAddress((void**)&wql, g_wql);
    cudaGetSymbolAddress((void**)&woh, g_woh);
    cudaGetSymbolAddress((void**)&wol, g_wol);
    cudaGetSymbolAddress((void**)&ath, g_ath);
    cudaGetSymbolAddress((void**)&atl, g_atl);

    cudaFuncSetAttribute(gemm_tc, cudaFuncAttributeMaxDynamicSharedMemorySize,
                         GEMM_DYN_SMEM);
    cudaFuncSetAttribute(attn_kernel, cudaFuncAttributeMaxDynamicSharedMemorySize,
                         ATTN_SMEM_BYTES);

    // 0) split x, transpose+split weights
    {
        int n4 = (M1 * DIM) / 4;
        split_kernel<<<(n4 + 255) / 256, 256>>>(x, xh, xl, n4);
        dim3 tb(32, 8);
        tsplit_kernel<<<dim3(QKVC / 32, DIM / 32), tb>>>(Wqkv, wqh, wql, DIM, QKVC);
        tsplit_kernel<<<dim3(DIM  / 32, DIM / 32), tb>>>(Wout, woh, wol, DIM, DIM);
    }
    // 1) QKV projection: [16384,1024] x [1024,3072]
    gemm_tc<<<dim3(QKVC / 128, M1 / 128), GK_THREADS, GEMM_DYN_SMEM>>>(
        DIM, QKVC, xh, xl, wqh, wql, qkv);
    // 2) windowed attention with RoPE
    attn_kernel<<<B_ * H_ * NW, 128, ATTN_SMEM_BYTES>>>();
    // 3) output projection: [16384,1024] x [1024,1024]
    gemm_tc<<<dim3(DIM / 128, M1 / 128), GK_THREADS, GEMM_DYN_SMEM>>>(
        DIM, DIM, ath, atl, woh, wol, out);
}

// round 12
// speedup vs baseline: 5.4764x; 1.6899x over previous
#include <cuda_runtime.h>
#include <cuda_bf16.h>
#include <math.h>
#include <float.h>
#include <stdint.h>

// ---------------------------------------------------------------------------
// Problem constants
// ---------------------------------------------------------------------------
#define B_    4
#define NSEQ  4096
#define DIM   1024
#define H_    16
#define DH    64
#define WS    128
#define NW    32          // NSEQ / WS
#define JW    256
#define QKVC  3072
#define M1    (B_ * NSEQ) // 16384
#define BH    (B_ * H_)   // 64

// ---------------------------------------------------------------------------
// Scratch (no cudaMalloc allowed)
// ---------------------------------------------------------------------------
__device__ float          g_qkv [(size_t)M1 * QKVC];    // fp32 qkv (GEMM1 out)
__device__ __nv_bfloat16  g_xh  [(size_t)M1 * DIM];
__device__ __nv_bfloat16  g_xl  [(size_t)M1 * DIM];
__device__ __nv_bfloat16  g_wqh [(size_t)QKVC * DIM];
__device__ __nv_bfloat16  g_wql [(size_t)QKVC * DIM];
__device__ __nv_bfloat16  g_woh [(size_t)DIM * DIM];
__device__ __nv_bfloat16  g_wol [(size_t)DIM * DIM];
__device__ __nv_bfloat16  g_ath [(size_t)M1 * DIM];     // attention out hi
__device__ __nv_bfloat16  g_atl [(size_t)M1 * DIM];     // attention out lo

// RoPE'd bf16 hi/lo tensors, layout [(b*H + h)*NSEQ + n][64]
#define QKV_E ((size_t)BH * NSEQ * DH)
__device__ __nv_bfloat16  g_qh [QKV_E], g_ql [QKV_E];
__device__ __nv_bfloat16  g_k0h[QKV_E], g_k0l[QKV_E];   // K rot(pos = n%128)
__device__ __nv_bfloat16  g_k1h[QKV_E], g_k1l[QKV_E];   // K rot(pos = n%128+128)
__device__ __nv_bfloat16  g_vh [QKV_E], g_vl [QKV_E];
__device__ float          g_cs [256 * 32 * 2];          // [pos][m][cos,sin]

// ---------------------------------------------------------------------------
// PTX helpers (sm_80-era; valid on base sm_103 target)
// ---------------------------------------------------------------------------
__device__ __forceinline__ uint32_t smem_to_u32(const void* p) {
    uint32_t a;
    asm("{ .reg .u64 t; cvta.to.shared.u64 t, %1; cvt.u32.u64 %0, t; }"
        : "=r"(a) : "l"(p));
    return a;
}
__device__ __forceinline__ void ldsm_x4(uint32_t& r0, uint32_t& r1,
                                        uint32_t& r2, uint32_t& r3, uint32_t a) {
    asm volatile("ldmatrix.sync.aligned.m8n8.x4.shared.b16 {%0,%1,%2,%3}, [%4];"
        : "=r"(r0), "=r"(r1), "=r"(r2), "=r"(r3) : "r"(a));
}
__device__ __forceinline__ void ldsm_x4t(uint32_t& r0, uint32_t& r1,
                                         uint32_t& r2, uint32_t& r3, uint32_t a) {
    asm volatile("ldmatrix.sync.aligned.m8n8.x4.trans.shared.b16 {%0,%1,%2,%3}, [%4];"
        : "=r"(r0), "=r"(r1), "=r"(r2), "=r"(r3) : "r"(a));
}
__device__ __forceinline__ void mma_bf16(float* d, const uint32_t* a,
                                         uint32_t b0, uint32_t b1) {
    asm volatile(
        "mma.sync.aligned.m16n8k16.row.col.f32.bf16.bf16.f32 "
        "{%0,%1,%2,%3}, {%4,%5,%6,%7}, {%8,%9}, {%0,%1,%2,%3};"
        : "+f"(d[0]), "+f"(d[1]), "+f"(d[2]), "+f"(d[3])
        : "r"(a[0]), "r"(a[1]), "r"(a[2]), "r"(a[3]), "r"(b0), "r"(b1));
}
__device__ __forceinline__ void cp_async16(uint32_t dst, const void* src) {
    asm volatile("cp.async.cg.shared.global [%0], [%1], 16;" :: "r"(dst), "l"(src));
}
#define CP_COMMIT() asm volatile("cp.async.commit_group;" ::: "memory")
#define CP_WAIT(n)  asm volatile("cp.async.wait_group %0;" :: "n"(n) : "memory")

__device__ __forceinline__ uint32_t pack_bf16(float a, float b) {
    __nv_bfloat162 t = __floats2bfloat162_rn(a, b);
    return *(uint32_t*)&t;
}

// ---------------------------------------------------------------------------
// Prep: fp32 -> bf16 hi/lo split; transposed split for weights
// ---------------------------------------------------------------------------
__global__ __launch_bounds__(256) void split_kernel(
    const float* __restrict__ src,
    __nv_bfloat16* __restrict__ hi, __nv_bfloat16* __restrict__ lo, int n4)
{
    int i = blockIdx.x * blockDim.x + threadIdx.x;
    if (i >= n4) return;
    float4 v = ((const float4*)src)[i];
    __nv_bfloat16 h0 = __float2bfloat16(v.x), h1 = __float2bfloat16(v.y);
    __nv_bfloat16 h2 = __float2bfloat16(v.z), h3 = __float2bfloat16(v.w);
    ((__nv_bfloat162*)hi)[i*2]   = __halves2bfloat162(h0, h1);
    ((__nv_bfloat162*)hi)[i*2+1] = __halves2bfloat162(h2, h3);
    ((__nv_bfloat162*)lo)[i*2]   = __halves2bfloat162(
        __float2bfloat16(v.x - __bfloat162float(h0)),
        __float2bfloat16(v.y - __bfloat162float(h1)));
    ((__nv_bfloat162*)lo)[i*2+1] = __halves2bfloat162(
        __float2bfloat16(v.z - __bfloat162float(h2)),
        __float2bfloat16(v.w - __bfloat162float(h3)));
}

__global__ __launch_bounds__(256) void tsplit_kernel(
    const float* __restrict__ W,
    __nv_bfloat16* __restrict__ Th, __nv_bfloat16* __restrict__ Tl, int K, int N)
{
    __shared__ float t[32][33];
    int x0 = blockIdx.x * 32, y0 = blockIdx.y * 32;
    int tx = threadIdx.x, ty = threadIdx.y;
    #pragma unroll
    for (int r = ty; r < 32; r += 8)
        t[r][tx] = W[(size_t)(y0 + r) * N + x0 + tx];
    __syncthreads();
    #pragma unroll
    for (int r = ty; r < 32; r += 8) {
        float v = t[tx][r];
        __nv_bfloat16 h = __float2bfloat16(v);
        size_t o = (size_t)(x0 + r) * K + y0 + tx;
        Th[o] = h;
        Tl[o] = __float2bfloat16(v - __bfloat162float(h));
    }
}

// trig table: pos 0..255, m 0..31
__global__ __launch_bounds__(256) void trig_kernel()
{
    int t = blockIdx.x * 256 + threadIdx.x; // 0..8191
    int pos = t >> 5, m = t & 31;
    const float RC = 0.28782313662425575f;  // ln(10000)/32
    float f = (float)pos * __expf(-(float)m * RC);
    float s, c;
    __sincosf(f, &s, &c);
    g_cs[(pos * 32 + m) * 2]     = c;
    g_cs[(pos * 32 + m) * 2 + 1] = s;
}

// RoPE + split: one block per row n; 512 threads = (h 0..15) x (m 0..31)
__global__ __launch_bounds__(512) void rope_kernel()
{
    int r  = blockIdx.x;          // 0..16383
    int b  = r >> 12, nn = r & 4095;
    int h  = threadIdx.x >> 5, m = threadIdx.x & 31;
    int pl = nn & 127;

    const float* row = &g_qkv[(size_t)r * QKVC + h * DH + m];
    float q0 = row[0],        q1 = row[32];
    float k0 = row[DIM],      k1 = row[DIM + 32];
    float v0 = row[2 * DIM],  v1 = row[2 * DIM + 32];

    float c0 = g_cs[(pl * 32 + m) * 2],         s0 = g_cs[(pl * 32 + m) * 2 + 1];
    float c1 = g_cs[((pl + 128) * 32 + m) * 2], s1 = g_cs[((pl + 128) * 32 + m) * 2 + 1];

    size_t o = ((size_t)(b * H_ + h) * NSEQ + nn) * DH + m;

    // Q: pos = 128 + nn%128, scaled by dh^-0.5
    float a0 = (q0 * c1 - q1 * s1) * 0.125f;
    float a1 = (q1 * c1 + q0 * s1) * 0.125f;
    __nv_bfloat16 hh = __float2bfloat16(a0);
    g_qh[o] = hh;       g_ql[o] = __float2bfloat16(a0 - __bfloat162float(hh));
    hh = __float2bfloat16(a1);
    g_qh[o + 32] = hh;  g_ql[o + 32] = __float2bfloat16(a1 - __bfloat162float(hh));

    // K copy0: pos = nn%128
    a0 = k0 * c0 - k1 * s0;  a1 = k1 * c0 + k0 * s0;
    hh = __float2bfloat16(a0);
    g_k0h[o] = hh;      g_k0l[o] = __float2bfloat16(a0 - __bfloat162float(hh));
    hh = __float2bfloat16(a1);
    g_k0h[o + 32] = hh; g_k0l[o + 32] = __float2bfloat16(a1 - __bfloat162float(hh));

    // K copy1: pos = nn%128 + 128
    a0 = k0 * c1 - k1 * s1;  a1 = k1 * c1 + k0 * s1;
    hh = __float2bfloat16(a0);
    g_k1h[o] = hh;      g_k1l[o] = __float2bfloat16(a0 - __bfloat162float(hh));
    hh = __float2bfloat16(a1);
    g_k1h[o + 32] = hh; g_k1l[o + 32] = __float2bfloat16(a1 - __bfloat162float(hh));

    // V: plain split
    hh = __float2bfloat16(v0);
    g_vh[o] = hh;       g_vl[o] = __float2bfloat16(v0 - __bfloat162float(hh));
    hh = __float2bfloat16(v1);
    g_vh[o + 32] = hh;  g_vl[o + 32] = __float2bfloat16(v1 - __bfloat162float(hh));
}

// ---------------------------------------------------------------------------
// HMMA bf16 split-precision GEMM (unchanged structure; now 2 CTAs/SM)
// ---------------------------------------------------------------------------
#define GK_THREADS 256
#define BKC        32
#define STAGES     3
#define TILE_B     8192
#define STAGE_B    (4 * TILE_B)
#define GEMM_DYN_SMEM (STAGES * STAGE_B)

__global__ __launch_bounds__(GK_THREADS, 2)
void gemm_tc(int K, int N,
             const __nv_bfloat16* __restrict__ Ah, const __nv_bfloat16* __restrict__ Al,
             const __nv_bfloat16* __restrict__ Bh, const __nv_bfloat16* __restrict__ Bl,
             float* __restrict__ C)
{
    extern __shared__ __align__(1024) char smem[];
    const uint32_t smemu = smem_to_u32(smem);

    const int tid  = threadIdx.x;
    const int lane = tid & 31;
    const int wid  = tid >> 5;
    const int wm   = wid & 1;
    const int wn   = wid >> 1;
    const int rowBase = blockIdx.y * 128;
    const int colBase = blockIdx.x * 128;
    const int NCH = K / BKC;

    const __nv_bfloat16* srcp[8];
    uint32_t dsto[8];
    {
        const __nv_bfloat16* bases[4] = {
            Ah + (size_t)rowBase * K, Al + (size_t)rowBase * K,
            Bh + (size_t)colBase * K, Bl + (size_t)colBase * K };
        #pragma unroll
        for (int i = 0; i < 8; ++i) {
            int g = i * GK_THREADS + tid;
            int tile = g >> 9, idx = g & 511, r = idx >> 2, c = idx & 3;
            srcp[i] = bases[tile] + (size_t)r * K + c * 8;
            dsto[i] = tile * TILE_B + r * 64 + ((c ^ ((r >> 1) & 3)) << 4);
        }
    }
    auto load_stage = [&](int st) {
        const uint32_t sb = smemu + st * STAGE_B;
        #pragma unroll
        for (int i = 0; i < 8; ++i) { cp_async16(sb + dsto[i], srcp[i]); srcp[i] += BKC; }
    };

    float acc[4][4][4];
    #pragma unroll
    for (int a = 0; a < 4; ++a)
        #pragma unroll
        for (int b = 0; b < 4; ++b)
            #pragma unroll
            for (int d = 0; d < 4; ++d) acc[a][b][d] = 0.0f;

    #pragma unroll
    for (int s = 0; s < STAGES - 1; ++s) { load_stage(s); CP_COMMIT(); }

    const int rA = lane & 15;
    const int kq = lane >> 4;

    for (int c = 0; c < NCH; ++c) {
        CP_WAIT(STAGES - 2);
        __syncthreads();
        if (c + STAGES - 1 < NCH) load_stage((c + STAGES - 1) % STAGES);
        CP_COMMIT();

        const uint32_t stA = smemu + (c % STAGES) * STAGE_B;
        const uint32_t stB = stA + 2 * TILE_B;

        #pragma unroll
        for (int ks = 0; ks < 2; ++ks) {
            uint32_t ah[4][4], al[4][4], bh[2][4], bl[2][4];
            #pragma unroll
            for (int mt = 0; mt < 4; ++mt) {
                int row = wm * 64 + mt * 16 + rA;
                uint32_t addr = stA + row * 64 + (((ks * 2 + kq) ^ ((row >> 1) & 3)) << 4);
                ldsm_x4(ah[mt][0], ah[mt][1], ah[mt][2], ah[mt][3], addr);
                ldsm_x4(al[mt][0], al[mt][1], al[mt][2], al[mt][3], addr + TILE_B);
            }
            #pragma unroll
            for (int t = 0; t < 2; ++t) {
                int row = wn * 32 + t * 16 + rA;
                uint32_t addr = stB + row * 64 + (((ks * 2 + kq) ^ ((row >> 1) & 3)) << 4);
                ldsm_x4(bh[t][0], bh[t][1], bh[t][2], bh[t][3], addr);
                ldsm_x4(bl[t][0], bl[t][1], bl[t][2], bl[t][3], addr + TILE_B);
            }
            #pragma unroll
            for (int mt = 0; mt < 4; ++mt)
                #pragma unroll
                for (int t = 0; t < 2; ++t) {
                    mma_bf16(acc[mt][2*t],   ah[mt], bh[t][0], bh[t][2]);
                    mma_bf16(acc[mt][2*t],   ah[mt], bl[t][0], bl[t][2]);
                    mma_bf16(acc[mt][2*t],   al[mt], bh[t][0], bh[t][2]);
                    mma_bf16(acc[mt][2*t+1], ah[mt], bh[t][1], bh[t][3]);
                    mma_bf16(acc[mt][2*t+1], ah[mt], bl[t][1], bl[t][3]);
                    mma_bf16(acc[mt][2*t+1], al[mt], bh[t][1], bh[t][3]);
                }
        }
    }

    #pragma unroll
    for (int mt = 0; mt < 4; ++mt) {
        int row0 = rowBase + wm * 64 + mt * 16 + (lane >> 2);
        #pragma unroll
        for (int nt = 0; nt < 4; ++nt) {
            int col = colBase + wn * 32 + nt * 8 + (lane & 3) * 2;
            *(float2*)&C[(size_t)row0 * N + col] = make_float2(acc[mt][nt][0], acc[mt][nt][1]);
            *(float2*)&C[(size_t)(row0+8) * N + col] = make_float2(acc[mt][nt][2], acc[mt][nt][3]);
        }
    }
}

// ---------------------------------------------------------------------------
// MMA flash-style local attention. One block per (b,h,w). 256 threads, 8 warps.
// Warp wr owns rows [16wr, 16wr+16). S = Q K^T (split bf16, 3 terms), softmax
// in registers, P*V via C-frag->A-frag identity + ldmatrix.trans on V.
// smem rows are 64 bf16 = 128 B; chunk swizzle c ^= (row & 7).
// ---------------------------------------------------------------------------
#define SQH 0
#define SQL 16384
#define SKH 32768
#define SKL 65536
#define SVH 98304
#define SVL 131072
#define ATTN_SMEM 163840

__global__ __launch_bounds__(256) void attn_kernel()
{
    extern __shared__ __align__(1024) char asm_[];
    const uint32_t sb = smem_to_u32(asm_);

    const int blk = blockIdx.x;
    const int w = blk & (NW - 1);
    const int h = (blk >> 5) & (H_ - 1);
    const int b = blk >> 9;
    const int tid  = threadIdx.x;
    const int lane = tid & 31;
    const int wr   = tid >> 5;

    const size_t bh_off = (size_t)(b * H_ + h) * NSEQ;

    // ---- cp.async loads: Q(2048) K(4096) V(4096) 16B chunks, 40/thread ----
    {
        // Q
        #pragma unroll
        for (int it = 0; it < 8; ++it) {
            int g = it * 256 + tid;
            int arr = g >> 10, r = (g >> 3) & 127, c = g & 7;
            const __nv_bfloat16* src = (arr ? g_ql : g_qh)
                + (bh_off + w * WS + r) * DH + c * 8;
            cp_async16(sb + (arr ? SQL : SQH) + r * 128 + ((c ^ (r & 7)) << 4), src);
        }
        // K
        #pragma unroll
        for (int it = 0; it < 16; ++it) {
            int g = it * 256 + tid;
            int arr = g >> 11, j = (g >> 3) & 255, c = g & 7;
            int n = (w == 0 && j < 128) ? j : (w - 1) * WS + j;
            const __nv_bfloat16* base =
                (j < 128) ? (arr ? g_k0l : g_k0h) : (arr ? g_k1l : g_k1h);
            cp_async16(sb + (arr ? SKL : SKH) + j * 128 + ((c ^ (j & 7)) << 4),
                       base + (bh_off + n) * DH + c * 8);
        }
        // V
        #pragma unroll
        for (int it = 0; it < 16; ++it) {
            int g = it * 256 + tid;
            int arr = g >> 11, j = (g >> 3) & 255, c = g & 7;
            int n = (w == 0 && j < 128) ? j : (w - 1) * WS + j;
            cp_async16(sb + (arr ? SVL : SVH) + j * 128 + ((c ^ (j & 7)) << 4),
                       (arr ? g_vl : g_vh) + (bh_off + n) * DH + c * 8);
        }
    }
    CP_COMMIT();
    CP_WAIT(0);
    __syncthreads();

    const int row0 = 16 * wr;
    const int nb0  = (w == 0) ? 8 : wr;        // first valid 16-key block
    const int NB   = (w == 0) ? wr + 1 : 9;    // number of valid blocks (<=9)

    // ---- S = Q K^T, band only: sacc[nb][t2*4 + d] -----------------------
    float sacc[9][8];
    #pragma unroll
    for (int i = 0; i < 9; ++i)
        #pragma unroll
        for (int j = 0; j < 8; ++j) sacc[i][j] = 0.0f;

    #pragma unroll
    for (int ks = 0; ks < 4; ++ks) {
        uint32_t aqh[4], aql[4];
        {
            int r = row0 + (lane & 15);
            int ch = 2 * ks + (lane >> 4);
            uint32_t off = r * 128 + ((ch ^ (r & 7)) << 4);
            ldsm_x4(aqh[0], aqh[1], aqh[2], aqh[3], sb + SQH + off);
            ldsm_x4(aql[0], aql[1], aql[2], aql[3], sb + SQL + off);
        }
        #pragma unroll
        for (int nb = 0; nb < 9; ++nb) {
            if (nb >= NB) break;
            int kb = nb0 + nb;
            uint32_t bh[4], bl[4];
            int r = kb * 16 + (lane & 15);
            int ch = 2 * ks + (lane >> 4);
            uint32_t off = r * 128 + ((ch ^ (r & 7)) << 4);
            ldsm_x4(bh[0], bh[1], bh[2], bh[3], sb + SKH + off);
            ldsm_x4(bl[0], bl[1], bl[2], bl[3], sb + SKL + off);
            mma_bf16(sacc[nb],     aqh, bh[0], bh[2]);
            mma_bf16(sacc[nb],     aqh, bl[0], bl[2]);
            mma_bf16(sacc[nb],     aql, bh[0], bh[2]);
            mma_bf16(sacc[nb] + 4, aqh, bh[1], bh[3]);
            mma_bf16(sacc[nb] + 4, aqh, bl[1], bl[3]);
            mma_bf16(sacc[nb] + 4, aql, bh[1], bh[3]);
        }
    }

    // ---- masked softmax in registers ------------------------------------
    const int g  = lane >> 2;
    const int tq = lane & 3;
    const int i0 = row0 + g;
    const int i1 = i0 + 8;
    const int jlo0 = (w == 0) ? (i0 < 128 ? 128 : i0) : i0;
    const int jlo1 = (w == 0) ? (i1 < 128 ? 128 : i1) : i1;

    float mx0 = -FLT_MAX, mx1 = -FLT_MAX;
    #pragma unroll
    for (int nb = 0; nb < 9; ++nb) {
        if (nb >= NB) break;
        int cb = 16 * (nb0 + nb) + 2 * tq;
        #pragma unroll
        for (int t2 = 0; t2 < 2; ++t2)
            #pragma unroll
            for (int d = 0; d < 2; ++d) {
                int c = cb + 8 * t2 + d;
                if (c >= jlo0 && c <= i0 + 128) mx0 = fmaxf(mx0, sacc[nb][t2*4 + d]);
                if (c >= jlo1 && c <= i1 + 128) mx1 = fmaxf(mx1, sacc[nb][t2*4 + 2 + d]);
            }
    }
    mx0 = fmaxf(mx0, __shfl_xor_sync(0xffffffffu, mx0, 1));
    mx0 = fmaxf(mx0, __shfl_xor_sync(0xffffffffu, mx0, 2));
    mx1 = fmaxf(mx1, __shfl_xor_sync(0xffffffffu, mx1, 1));
    mx1 = fmaxf(mx1, __shfl_xor_sync(0xffffffffu, mx1, 2));

    float sum0 = 0.f, sum1 = 0.f;
    #pragma unroll
    for (int nb = 0; nb < 9; ++nb) {
        if (nb >= NB) break;
        int cb = 16 * (nb0 + nb) + 2 * tq;
        #pragma unroll
        for (int t2 = 0; t2 < 2; ++t2)
            #pragma unroll
            for (int d = 0; d < 2; ++d) {
                int c = cb + 8 * t2 + d;
                float e0 = (c >= jlo0 && c <= i0 + 128)
                         ? __expf(sacc[nb][t2*4 + d] - mx0) : 0.f;
                float e1 = (c >= jlo1 && c <= i1 + 128)
                         ? __expf(sacc[nb][t2*4 + 2 + d] - mx1) : 0.f;
                sacc[nb][t2*4 + d]     = e0;  sum0 += e0;
                sacc[nb][t2*4 + 2 + d] = e1;  sum1 += e1;
            }
    }
    sum0 += __shfl_xor_sync(0xffffffffu, sum0, 1);
    sum0 += __shfl_xor_sync(0xffffffffu, sum0, 2);
    sum1 += __shfl_xor_sync(0xffffffffu, sum1, 1);
    sum1 += __shfl_xor_sync(0xffffffffu, sum1, 2);
    const float inv0 = 1.0f / sum0;
    const float inv1 = 1.0f / sum1;

    // ---- O = P V (unnormalized P; scale at the end) ----------------------
    float oacc[8][4];
    #pragma unroll
    for (int i = 0; i < 8; ++i)
        #pragma unroll
        for (int j = 0; j < 4; ++j) oacc[i][j] = 0.0f;

    #pragma unroll
    for (int nb = 0; nb < 9; ++nb) {
        if (nb >= NB) break;
        int kb = nb0 + nb;
        // A fragments from softmaxed accumulator (C->A identity), hi/lo split
        uint32_t ph[4], pl[4];
        #pragma unroll
        for (int q = 0; q < 4; ++q) {
            float v0 = sacc[nb][q * 2], v1 = sacc[nb][q * 2 + 1];
            __nv_bfloat162 hi2 = __floats2bfloat162_rn(v0, v1);
            ph[q] = *(uint32_t*)&hi2;
            pl[q] = pack_bf16(v0 - __bfloat162float(__low2bfloat16(hi2)),
                              v1 - __bfloat162float(__high2bfloat16(hi2)));
        }
        #pragma unroll
        for (int dg = 0; dg < 4; ++dg) {
            int rrow = kb * 16 + (lane & 7) + ((lane >> 3) & 1) * 8;
            int ch   = 2 * dg + (lane >> 4);
            uint32_t off = rrow * 128 + ((ch ^ (rrow & 7)) << 4);
            uint32_t vh[4], vl[4];
            ldsm_x4t(vh[0], vh[1], vh[2], vh[3], sb + SVH + off);
            ldsm_x4t(vl[0], vl[1], vl[2], vl[3], sb + SVL + off);
            mma_bf16(oacc[2*dg],   ph, vh[0], vh[1]);
            mma_bf16(oacc[2*dg],   ph, vl[0], vl[1]);
            mma_bf16(oacc[2*dg],   pl, vh[0], vh[1]);
            mma_bf16(oacc[2*dg+1], ph, vh[2], vh[3]);
            mma_bf16(oacc[2*dg+1], ph, vl[2], vl[3]);
            mma_bf16(oacc[2*dg+1], pl, vh[2], vh[3]);
        }
    }

    // ---- write bf16 hi/lo output for GEMM2 -------------------------------
    const size_t ro0 = ((size_t)b * NSEQ + w * WS + i0) * DIM + h * DH;
    const size_t ro1 = ((size_t)b * NSEQ + w * WS + i1) * DIM + h * DH;
    #pragma unroll
    for (int nt = 0; nt < 8; ++nt) {
        int c0 = 8 * nt + 2 * tq;
        float o00 = oacc[nt][0] * inv0, o01 = oacc[nt][1] * inv0;
        float o10 = oacc[nt][2] * inv1, o11 = oacc[nt][3] * inv1;
        __nv_bfloat162 h0 = __floats2bfloat162_rn(o00, o01);
        __nv_bfloat162 h1 = __floats2bfloat162_rn(o10, o11);
        *(__nv_bfloat162*)&g_ath[ro0 + c0] = h0;
        *(__nv_bfloat162*)&g_ath[ro1 + c0] = h1;
        *(__nv_bfloat162*)&g_atl[ro0 + c0] = __floats2bfloat162_rn(
            o00 - __bfloat162float(__low2bfloat16(h0)),
            o01 - __bfloat162float(__high2bfloat16(h0)));
        *(__nv_bfloat162*)&g_atl[ro1 + c0] = __floats2bfloat162_rn(
            o10 - __bfloat162float(__low2bfloat16(h1)),
            o11 - __bfloat162float(__high2bfloat16(h1)));
    }
}

// ---------------------------------------------------------------------------
extern "C" void kernel_launch(void* const* d_in, const int* in_sizes, int n_in,
                              void* d_out, int out_size)
{
    const float* x    = (const float*)d_in[0];
    const float* Wqkv = (const float*)d_in[1];
    const float* Wout = (const float*)d_in[2];
    float* out = (float*)d_out;

    float *qkv;
    __nv_bfloat16 *xh, *xl, *wqh, *wql, *woh, *wol, *ath, *atl;
    cudaGetSymbolAddress((void**)&qkv, g_qkv);
    cudaGetSymbolAddress((void**)&xh,  g_xh);
    cudaGetSymbolAddress((void**)&xl,  g_xl);
    cudaGetSymbolAddress((void**)&wqh, g_wqh);
    cudaGetSymbolAddress((void**)&wql, g_wql);
    cudaGetSymbolAddress((void**)&woh, g_woh);
    cudaGetSymbolAddress((void**)&wol, g_wol);
    cudaGetSymbolAddress((void**)&ath, g_ath);
    cudaGetSymbolAddress((void**)&atl, g_atl);

    cudaFuncSetAttribute(gemm_tc, cudaFuncAttributeMaxDynamicSharedMemorySize,
                         GEMM_DYN_SMEM);
    cudaFuncSetAttribute(attn_kernel, cudaFuncAttributeMaxDynamicSharedMemorySize,
                         ATTN_SMEM);

    // 0) prep: trig table, x split, weight transpose+split
    trig_kernel<<<32, 256>>>();
    {
        int n4 = (M1 * DIM) / 4;
        split_kernel<<<(n4 + 255) / 256, 256>>>(x, xh, xl, n4);
        dim3 tb(32, 8);
        tsplit_kernel<<<dim3(QKVC / 32, DIM / 32), tb>>>(Wqkv, wqh, wql, DIM, QKVC);
        tsplit_kernel<<<dim3(DIM  / 32, DIM / 32), tb>>>(Wout, woh, wol, DIM, DIM);
    }
    // 1) QKV projection
    gemm_tc<<<dim3(QKVC / 128, M1 / 128), GK_THREADS, GEMM_DYN_SMEM>>>(
        DIM, QKVC, xh, xl, wqh, wql, qkv);
    // 2) RoPE + bf16 split of q/k/v
    rope_kernel<<<M1, 512>>>();
    // 3) MMA local attention
    attn_kernel<<<B_ * H_ * NW, 256, ATTN_SMEM>>>();
    // 4) output projection
    gemm_tc<<<dim3(DIM / 128, M1 / 128), GK_THREADS, GEMM_DYN_SMEM>>>(
        DIM, DIM, ath, atl, woh, wol, out);
}

// round 15
// speedup vs baseline: 5.6665x; 1.0347x over previous
#include <cuda_runtime.h>
#include <cuda_bf16.h>
#include <math.h>
#include <float.h>
#include <stdint.h>

// ---------------------------------------------------------------------------
// Problem constants
// ---------------------------------------------------------------------------
#define B_    4
#define NSEQ  4096
#define DIM   1024
#define H_    16
#define DH    64
#define WS    128
#define NW    32          // NSEQ / WS
#define QKVC  3072
#define M1    (B_ * NSEQ) // 16384
#define BH    (B_ * H_)   // 64

// ---------------------------------------------------------------------------
// Scratch (no cudaMalloc allowed)
// ---------------------------------------------------------------------------
__device__ float          g_qkv [(size_t)M1 * QKVC];    // fp32 qkv (GEMM1 out)
__device__ __nv_bfloat16  g_xh  [(size_t)M1 * DIM];
__device__ __nv_bfloat16  g_xl  [(size_t)M1 * DIM];
__device__ __nv_bfloat16  g_wqh [(size_t)QKVC * DIM];
__device__ __nv_bfloat16  g_wql [(size_t)QKVC * DIM];
__device__ __nv_bfloat16  g_woh [(size_t)DIM * DIM];
__device__ __nv_bfloat16  g_wol [(size_t)DIM * DIM];
__device__ __nv_bfloat16  g_ath [(size_t)M1 * DIM];     // attention out hi
__device__ __nv_bfloat16  g_atl [(size_t)M1 * DIM];     // attention out lo
__device__ float          g_cs  [256 * 32 * 2];         // [pos][m][cos,sin]

// ---------------------------------------------------------------------------
// PTX helpers (sm_80-era; valid on base sm_103 target)
// ---------------------------------------------------------------------------
__device__ __forceinline__ uint32_t smem_to_u32(const void* p) {
    uint32_t a;
    asm("{ .reg .u64 t; cvta.to.shared.u64 t, %1; cvt.u32.u64 %0, t; }"
        : "=r"(a) : "l"(p));
    return a;
}
__device__ __forceinline__ void ldsm_x4(uint32_t& r0, uint32_t& r1,
                                        uint32_t& r2, uint32_t& r3, uint32_t a) {
    asm volatile("ldmatrix.sync.aligned.m8n8.x4.shared.b16 {%0,%1,%2,%3}, [%4];"
        : "=r"(r0), "=r"(r1), "=r"(r2), "=r"(r3) : "r"(a));
}
__device__ __forceinline__ void ldsm_x4t(uint32_t& r0, uint32_t& r1,
                                         uint32_t& r2, uint32_t& r3, uint32_t a) {
    asm volatile("ldmatrix.sync.aligned.m8n8.x4.trans.shared.b16 {%0,%1,%2,%3}, [%4];"
        : "=r"(r0), "=r"(r1), "=r"(r2), "=r"(r3) : "r"(a));
}
__device__ __forceinline__ void mma_bf16(float* d, const uint32_t* a,
                                         uint32_t b0, uint32_t b1) {
    asm volatile(
        "mma.sync.aligned.m16n8k16.row.col.f32.bf16.bf16.f32 "
        "{%0,%1,%2,%3}, {%4,%5,%6,%7}, {%8,%9}, {%0,%1,%2,%3};"
        : "+f"(d[0]), "+f"(d[1]), "+f"(d[2]), "+f"(d[3])
        : "r"(a[0]), "r"(a[1]), "r"(a[2]), "r"(a[3]), "r"(b0), "r"(b1));
}
__device__ __forceinline__ void cp_async16(uint32_t dst, const void* src) {
    asm volatile("cp.async.cg.shared.global [%0], [%1], 16;" :: "r"(dst), "l"(src));
}
#define CP_COMMIT() asm volatile("cp.async.commit_group;" ::: "memory")
#define CP_WAIT(n)  asm volatile("cp.async.wait_group %0;" :: "n"(n) : "memory")

__device__ __forceinline__ uint32_t pack_bf16(float a, float b) {
    __nv_bfloat162 t = __floats2bfloat162_rn(a, b);
    return *(uint32_t*)&t;
}

// ---------------------------------------------------------------------------
// Prep: fp32 -> bf16 hi/lo split; transposed split for weights; trig table
// ---------------------------------------------------------------------------
__global__ __launch_bounds__(256) void split_kernel(
    const float* __restrict__ src,
    __nv_bfloat16* __restrict__ hi, __nv_bfloat16* __restrict__ lo, int n4)
{
    int i = blockIdx.x * blockDim.x + threadIdx.x;
    if (i >= n4) return;
    float4 v = ((const float4*)src)[i];
    __nv_bfloat16 h0 = __float2bfloat16(v.x), h1 = __float2bfloat16(v.y);
    __nv_bfloat16 h2 = __float2bfloat16(v.z), h3 = __float2bfloat16(v.w);
    ((__nv_bfloat162*)hi)[i*2]   = __halves2bfloat162(h0, h1);
    ((__nv_bfloat162*)hi)[i*2+1] = __halves2bfloat162(h2, h3);
    ((__nv_bfloat162*)lo)[i*2]   = __halves2bfloat162(
        __float2bfloat16(v.x - __bfloat162float(h0)),
        __float2bfloat16(v.y - __bfloat162float(h1)));
    ((__nv_bfloat162*)lo)[i*2+1] = __halves2bfloat162(
        __float2bfloat16(v.z - __bfloat162float(h2)),
        __float2bfloat16(v.w - __bfloat162float(h3)));
}

__global__ __launch_bounds__(256) void tsplit_kernel(
    const float* __restrict__ W,
    __nv_bfloat16* __restrict__ Th, __nv_bfloat16* __restrict__ Tl, int K, int N)
{
    __shared__ float t[32][33];
    int x0 = blockIdx.x * 32, y0 = blockIdx.y * 32;
    int tx = threadIdx.x, ty = threadIdx.y;
    #pragma unroll
    for (int r = ty; r < 32; r += 8)
        t[r][tx] = W[(size_t)(y0 + r) * N + x0 + tx];
    __syncthreads();
    #pragma unroll
    for (int r = ty; r < 32; r += 8) {
        float v = t[tx][r];
        __nv_bfloat16 h = __float2bfloat16(v);
        size_t o = (size_t)(x0 + r) * K + y0 + tx;
        Th[o] = h;
        Tl[o] = __float2bfloat16(v - __bfloat162float(h));
    }
}

__global__ __launch_bounds__(256) void trig_kernel()
{
    int t = blockIdx.x * 256 + threadIdx.x; // 0..8191
    int pos = t >> 5, m = t & 31;
    const float RC = 0.28782313662425575f;  // ln(10000)/32
    float f = (float)pos * __expf(-(float)m * RC);
    float s, c;
    __sincosf(f, &s, &c);
    g_cs[(pos * 32 + m) * 2]     = c;
    g_cs[(pos * 32 + m) * 2 + 1] = s;
}

// ---------------------------------------------------------------------------
// HMMA bf16 split-precision GEMM (2 CTAs/SM)
// ---------------------------------------------------------------------------
#define GK_THREADS 256
#define BKC        32
#define STAGES     3
#define TILE_B     8192
#define STAGE_B    (4 * TILE_B)
#define GEMM_DYN_SMEM (STAGES * STAGE_B)

__global__ __launch_bounds__(GK_THREADS, 2)
void gemm_tc(int K, int N,
             const __nv_bfloat16* __restrict__ Ah, const __nv_bfloat16* __restrict__ Al,
             const __nv_bfloat16* __restrict__ Bh, const __nv_bfloat16* __restrict__ Bl,
             float* __restrict__ C)
{
    extern __shared__ __align__(1024) char smem[];
    const uint32_t smemu = smem_to_u32(smem);

    const int tid  = threadIdx.x;
    const int lane = tid & 31;
    const int wid  = tid >> 5;
    const int wm   = wid & 1;
    const int wn   = wid >> 1;
    const int rowBase = blockIdx.y * 128;
    const int colBase = blockIdx.x * 128;
    const int NCH = K / BKC;

    const __nv_bfloat16* srcp[8];
    uint32_t dsto[8];
    {
        const __nv_bfloat16* bases[4] = {
            Ah + (size_t)rowBase * K, Al + (size_t)rowBase * K,
            Bh + (size_t)colBase * K, Bl + (size_t)colBase * K };
        #pragma unroll
        for (int i = 0; i < 8; ++i) {
            int g = i * GK_THREADS + tid;
            int tile = g >> 9, idx = g & 511, r = idx >> 2, c = idx & 3;
            srcp[i] = bases[tile] + (size_t)r * K + c * 8;
            dsto[i] = tile * TILE_B + r * 64 + ((c ^ ((r >> 1) & 3)) << 4);
        }
    }
    auto load_stage = [&](int st) {
        const uint32_t sb = smemu + st * STAGE_B;
        #pragma unroll
        for (int i = 0; i < 8; ++i) { cp_async16(sb + dsto[i], srcp[i]); srcp[i] += BKC; }
    };

    float acc[4][4][4];
    #pragma unroll
    for (int a = 0; a < 4; ++a)
        #pragma unroll
        for (int b = 0; b < 4; ++b)
            #pragma unroll
            for (int d = 0; d < 4; ++d) acc[a][b][d] = 0.0f;

    #pragma unroll
    for (int s = 0; s < STAGES - 1; ++s) { load_stage(s); CP_COMMIT(); }

    const int rA = lane & 15;
    const int kq = lane >> 4;

    for (int c = 0; c < NCH; ++c) {
        CP_WAIT(STAGES - 2);
        __syncthreads();
        if (c + STAGES - 1 < NCH) load_stage((c + STAGES - 1) % STAGES);
        CP_COMMIT();

        const uint32_t stA = smemu + (c % STAGES) * STAGE_B;
        const uint32_t stB = stA + 2 * TILE_B;

        #pragma unroll
        for (int ks = 0; ks < 2; ++ks) {
            uint32_t ah[4][4], al[4][4], bh[2][4], bl[2][4];
            #pragma unroll
            for (int mt = 0; mt < 4; ++mt) {
                int row = wm * 64 + mt * 16 + rA;
                uint32_t addr = stA + row * 64 + (((ks * 2 + kq) ^ ((row >> 1) & 3)) << 4);
                ldsm_x4(ah[mt][0], ah[mt][1], ah[mt][2], ah[mt][3], addr);
                ldsm_x4(al[mt][0], al[mt][1], al[mt][2], al[mt][3], addr + TILE_B);
            }
            #pragma unroll
            for (int t = 0; t < 2; ++t) {
                int row = wn * 32 + t * 16 + rA;
                uint32_t addr = stB + row * 64 + (((ks * 2 + kq) ^ ((row >> 1) & 3)) << 4);
                ldsm_x4(bh[t][0], bh[t][1], bh[t][2], bh[t][3], addr);
                ldsm_x4(bl[t][0], bl[t][1], bl[t][2], bl[t][3], addr + TILE_B);
            }
            #pragma unroll
            for (int mt = 0; mt < 4; ++mt)
                #pragma unroll
                for (int t = 0; t < 2; ++t) {
                    mma_bf16(acc[mt][2*t],   ah[mt], bh[t][0], bh[t][2]);
                    mma_bf16(acc[mt][2*t],   ah[mt], bl[t][0], bl[t][2]);
                    mma_bf16(acc[mt][2*t],   al[mt], bh[t][0], bh[t][2]);
                    mma_bf16(acc[mt][2*t+1], ah[mt], bh[t][1], bh[t][3]);
                    mma_bf16(acc[mt][2*t+1], ah[mt], bl[t][1], bl[t][3]);
                    mma_bf16(acc[mt][2*t+1], al[mt], bh[t][1], bh[t][3]);
                }
        }
    }

    #pragma unroll
    for (int mt = 0; mt < 4; ++mt) {
        int row0 = rowBase + wm * 64 + mt * 16 + (lane >> 2);
        #pragma unroll
        for (int nt = 0; nt < 4; ++nt) {
            int col = colBase + wn * 32 + nt * 8 + (lane & 3) * 2;
            *(float2*)&C[(size_t)row0 * N + col] = make_float2(acc[mt][nt][0], acc[mt][nt][1]);
            *(float2*)&C[(size_t)(row0+8) * N + col] = make_float2(acc[mt][nt][2], acc[mt][nt][3]);
        }
    }
}

// ---------------------------------------------------------------------------
// MMA flash-style local attention with FUSED RoPE + bf16 split.
// One block per (b,h,w). 256 threads. Reads fp32 g_qkv directly; rotates
// Q (pos=128+i) and K (pos=j, window-relative) via g_cs table, splits to
// bf16 hi/lo in smem, then runs the R11 MMA/softmax/PV flow unchanged.
// ---------------------------------------------------------------------------
#define SQH 0
#define SQL 16384
#define SKH 32768
#define SKL 65536
#define SVH 98304
#define SVL 131072
#define ATTN_SMEM 163840

__global__ __launch_bounds__(256) void attn_kernel()
{
    extern __shared__ __align__(1024) char asm_[];
    const uint32_t sb = smem_to_u32(asm_);

    const int blk = blockIdx.x;
    const int w = blk & (NW - 1);
    const int h = (blk >> 5) & (H_ - 1);
    const int b = blk >> 9;
    const int tid  = threadIdx.x;
    const int lane = tid & 31;
    const int wr   = tid >> 5;

    // ---- fused load + RoPE + split: 640 rows (Q128, K256, V256) ----------
    {
        const int grp = tid >> 3;   // 0..31: row within iteration
        const int qd  = tid & 7;    // float4 index within 32-float half
        #pragma unroll
        for (int it = 0; it < 20; ++it) {
            int rid = it * 32 + grp;
            int kind = (rid < 128) ? 0 : (rid < 384 ? 1 : 2);
            int r = rid - ((kind == 0) ? 0 : (kind == 1 ? 128 : 384));
            int n, pos;
            uint32_t dH, dL;
            if (kind == 0) { n = w * WS + r;  pos = 128 + r; dH = SQH; dL = SQL; }
            else {
                n = (w == 0) ? r % WS : (w - 1) * WS + r;   // w==0 lower half masked
                pos = r;
                dH = (kind == 1) ? SKH : SVH;
                dL = (kind == 1) ? SKL : SVL;
            }
            const float* src = &g_qkv[(size_t)(b * NSEQ + n) * QKVC
                                      + kind * DIM + h * DH];
            float4 a  = *(const float4*)(src + qd * 4);
            float4 bq = *(const float4*)(src + 32 + qd * 4);
            float o0[4], o1[4];
            if (kind < 2) {
                const float4 cs0 = *(const float4*)&g_cs[(pos * 32 + qd * 4) * 2];
                const float4 cs1 = *(const float4*)&g_cs[(pos * 32 + qd * 4) * 2 + 4];
                float sc = (kind == 0) ? 0.125f : 1.0f;
                o0[0] = (a.x * cs0.x - bq.x * cs0.y) * sc;
                o1[0] = (bq.x * cs0.x + a.x * cs0.y) * sc;
                o0[1] = (a.y * cs0.z - bq.y * cs0.w) * sc;
                o1[1] = (bq.y * cs0.z + a.y * cs0.w) * sc;
                o0[2] = (a.z * cs1.x - bq.z * cs1.y) * sc;
                o1[2] = (bq.z * cs1.x + a.z * cs1.y) * sc;
                o0[3] = (a.w * cs1.z - bq.w * cs1.w) * sc;
                o1[3] = (bq.w * cs1.z + a.w * cs1.w) * sc;
            } else {
                o0[0] = a.x;  o0[1] = a.y;  o0[2] = a.z;  o0[3] = a.w;
                o1[0] = bq.x; o1[1] = bq.y; o1[2] = bq.z; o1[3] = bq.w;
            }
            // low half: cols 4qd..4qd+3 -> chunk qd>>1, byte (qd&1)*8
            uint32_t offL = r * 128 + ((((qd >> 1))     ^ (r & 7)) << 4) + (qd & 1) * 8;
            uint32_t offH = r * 128 + (((4 + (qd >> 1)) ^ (r & 7)) << 4) + (qd & 1) * 8;
            uint32_t h0 = pack_bf16(o0[0], o0[1]);
            uint32_t h1 = pack_bf16(o0[2], o0[3]);
            uint32_t h2 = pack_bf16(o1[0], o1[1]);
            uint32_t h3 = pack_bf16(o1[2], o1[3]);
            *(uint2*)(asm_ + dH + offL) = make_uint2(h0, h1);
            *(uint2*)(asm_ + dH + offH) = make_uint2(h2, h3);
            __nv_bfloat162* p0 = (__nv_bfloat162*)&h0;
            __nv_bfloat162* p1 = (__nv_bfloat162*)&h1;
            __nv_bfloat162* p2 = (__nv_bfloat162*)&h2;
            __nv_bfloat162* p3 = (__nv_bfloat162*)&h3;
            uint32_t l0 = pack_bf16(o0[0] - __bfloat162float(__low2bfloat16(*p0)),
                                    o0[1] - __bfloat162float(__high2bfloat16(*p0)));
            uint32_t l1 = pack_bf16(o0[2] - __bfloat162float(__low2bfloat16(*p1)),
                                    o0[3] - __bfloat162float(__high2bfloat16(*p1)));
            uint32_t l2 = pack_bf16(o1[0] - __bfloat162float(__low2bfloat16(*p2)),
                                    o1[1] - __bfloat162float(__high2bfloat16(*p2)));
            uint32_t l3 = pack_bf16(o1[2] - __bfloat162float(__low2bfloat16(*p3)),
                                    o1[3] - __bfloat162float(__high2bfloat16(*p3)));
            *(uint2*)(asm_ + dL + offL) = make_uint2(l0, l1);
            *(uint2*)(asm_ + dL + offH) = make_uint2(l2, l3);
        }
    }
    __syncthreads();

    const int row0 = 16 * wr;
    const int nb0  = (w == 0) ? 8 : wr;
    const int NB   = (w == 0) ? wr + 1 : 9;

    // ---- S = Q K^T, band only --------------------------------------------
    float sacc[9][8];
    #pragma unroll
    for (int i = 0; i < 9; ++i)
        #pragma unroll
        for (int j = 0; j < 8; ++j) sacc[i][j] = 0.0f;

    #pragma unroll
    for (int ks = 0; ks < 4; ++ks) {
        uint32_t aqh[4], aql[4];
        {
            int r = row0 + (lane & 15);
            int ch = 2 * ks + (lane >> 4);
            uint32_t off = r * 128 + ((ch ^ (r & 7)) << 4);
            ldsm_x4(aqh[0], aqh[1], aqh[2], aqh[3], sb + SQH + off);
            ldsm_x4(aql[0], aql[1], aql[2], aql[3], sb + SQL + off);
        }
        #pragma unroll
        for (int nb = 0; nb < 9; ++nb) {
            if (nb >= NB) break;
            int kb = nb0 + nb;
            uint32_t bh[4], bl[4];
            int r = kb * 16 + (lane & 15);
            int ch = 2 * ks + (lane >> 4);
            uint32_t off = r * 128 + ((ch ^ (r & 7)) << 4);
            ldsm_x4(bh[0], bh[1], bh[2], bh[3], sb + SKH + off);
            ldsm_x4(bl[0], bl[1], bl[2], bl[3], sb + SKL + off);
            mma_bf16(sacc[nb],     aqh, bh[0], bh[2]);
            mma_bf16(sacc[nb],     aqh, bl[0], bl[2]);
            mma_bf16(sacc[nb],     aql, bh[0], bh[2]);
            mma_bf16(sacc[nb] + 4, aqh, bh[1], bh[3]);
            mma_bf16(sacc[nb] + 4, aqh, bl[1], bl[3]);
            mma_bf16(sacc[nb] + 4, aql, bh[1], bh[3]);
        }
    }

    // ---- masked softmax in registers --------------------------------------
    const int g  = lane >> 2;
    const int tq = lane & 3;
    const int i0 = row0 + g;
    const int i1 = i0 + 8;
    const int jlo0 = (w == 0) ? (i0 < 128 ? 128 : i0) : i0;
    const int jlo1 = (w == 0) ? (i1 < 128 ? 128 : i1) : i1;

    float mx0 = -FLT_MAX, mx1 = -FLT_MAX;
    #pragma unroll
    for (int nb = 0; nb < 9; ++nb) {
        if (nb >= NB) break;
        int cb = 16 * (nb0 + nb) + 2 * tq;
        #pragma unroll
        for (int t2 = 0; t2 < 2; ++t2)
            #pragma unroll
            for (int d = 0; d < 2; ++d) {
                int c = cb + 8 * t2 + d;
                if (c >= jlo0 && c <= i0 + 128) mx0 = fmaxf(mx0, sacc[nb][t2*4 + d]);
                if (c >= jlo1 && c <= i1 + 128) mx1 = fmaxf(mx1, sacc[nb][t2*4 + 2 + d]);
            }
    }
    mx0 = fmaxf(mx0, __shfl_xor_sync(0xffffffffu, mx0, 1));
    mx0 = fmaxf(mx0, __shfl_xor_sync(0xffffffffu, mx0, 2));
    mx1 = fmaxf(mx1, __shfl_xor_sync(0xffffffffu, mx1, 1));
    mx1 = fmaxf(mx1, __shfl_xor_sync(0xffffffffu, mx1, 2));

    float sum0 = 0.f, sum1 = 0.f;
    #pragma unroll
    for (int nb = 0; nb < 9; ++nb) {
        if (nb >= NB) break;
        int cb = 16 * (nb0 + nb) + 2 * tq;
        #pragma unroll
        for (int t2 = 0; t2 < 2; ++t2)
            #pragma unroll
            for (int d = 0; d < 2; ++d) {
                int c = cb + 8 * t2 + d;
                float e0 = (c >= jlo0 && c <= i0 + 128)
                         ? __expf(sacc[nb][t2*4 + d] - mx0) : 0.f;
                float e1 = (c >= jlo1 && c <= i1 + 128)
                         ? __expf(sacc[nb][t2*4 + 2 + d] - mx1) : 0.f;
                sacc[nb][t2*4 + d]     = e0;  sum0 += e0;
                sacc[nb][t2*4 + 2 + d] = e1;  sum1 += e1;
            }
    }
    sum0 += __shfl_xor_sync(0xffffffffu, sum0, 1);
    sum0 += __shfl_xor_sync(0xffffffffu, sum0, 2);
    sum1 += __shfl_xor_sync(0xffffffffu, sum1, 1);
    sum1 += __shfl_xor_sync(0xffffffffu, sum1, 2);
    const float inv0 = 1.0f / sum0;
    const float inv1 = 1.0f / sum1;

    // ---- O = P V -----------------------------------------------------------
    float oacc[8][4];
    #pragma unroll
    for (int i = 0; i < 8; ++i)
        #pragma unroll
        for (int j = 0; j < 4; ++j) oacc[i][j] = 0.0f;

    #pragma unroll
    for (int nb = 0; nb < 9; ++nb) {
        if (nb >= NB) break;
        int kb = nb0 + nb;
        uint32_t ph[4], pl[4];
        #pragma unroll
        for (int q = 0; q < 4; ++q) {
            float v0 = sacc[nb][q * 2], v1 = sacc[nb][q * 2 + 1];
            __nv_bfloat162 hi2 = __floats2bfloat162_rn(v0, v1);
            ph[q] = *(uint32_t*)&hi2;
            pl[q] = pack_bf16(v0 - __bfloat162float(__low2bfloat16(hi2)),
                              v1 - __bfloat162float(__high2bfloat16(hi2)));
        }
        #pragma unroll
        for (int dg = 0; dg < 4; ++dg) {
            int rrow = kb * 16 + (lane & 7) + ((lane >> 3) & 1) * 8;
            int ch   = 2 * dg + (lane >> 4);
            uint32_t off = rrow * 128 + ((ch ^ (rrow & 7)) << 4);
            uint32_t vh[4], vl[4];
            ldsm_x4t(vh[0], vh[1], vh[2], vh[3], sb + SVH + off);
            ldsm_x4t(vl[0], vl[1], vl[2], vl[3], sb + SVL + off);
            mma_bf16(oacc[2*dg],   ph, vh[0], vh[1]);
            mma_bf16(oacc[2*dg],   ph, vl[0], vl[1]);
            mma_bf16(oacc[2*dg],   pl, vh[0], vh[1]);
            mma_bf16(oacc[2*dg+1], ph, vh[2], vh[3]);
            mma_bf16(oacc[2*dg+1], ph, vl[2], vl[3]);
            mma_bf16(oacc[2*dg+1], pl, vh[2], vh[3]);
        }
    }

    // ---- write bf16 hi/lo output for GEMM2 ---------------------------------
    const size_t ro0 = ((size_t)b * NSEQ + w * WS + i0) * DIM + h * DH;
    const size_t ro1 = ((size_t)b * NSEQ + w * WS + i1) * DIM + h * DH;
    #pragma unroll
    for (int nt = 0; nt < 8; ++nt) {
        int c0 = 8 * nt + 2 * tq;
        float o00 = oacc[nt][0] * inv0, o01 = oacc[nt][1] * inv0;
        float o10 = oacc[nt][2] * inv1, o11 = oacc[nt][3] * inv1;
        __nv_bfloat162 h0 = __floats2bfloat162_rn(o00, o01);
        __nv_bfloat162 h1 = __floats2bfloat162_rn(o10, o11);
        *(__nv_bfloat162*)&g_ath[ro0 + c0] = h0;
        *(__nv_bfloat162*)&g_ath[ro1 + c0] = h1;
        *(__nv_bfloat162*)&g_atl[ro0 + c0] = __floats2bfloat162_rn(
            o00 - __bfloat162float(__low2bfloat16(h0)),
            o01 - __bfloat162float(__high2bfloat16(h0)));
        *(__nv_bfloat162*)&g_atl[ro1 + c0] = __floats2bfloat162_rn(
            o10 - __bfloat162float(__low2bfloat16(h1)),
            o11 - __bfloat162float(__high2bfloat16(h1)));
    }
}

// ---------------------------------------------------------------------------
extern "C" void kernel_launch(void* const* d_in, const int* in_sizes, int n_in,
                              void* d_out, int out_size)
{
    const float* x    = (const float*)d_in[0];
    const float* Wqkv = (const float*)d_in[1];
    const float* Wout = (const float*)d_in[2];
    float* out = (float*)d_out;

    float *qkv;
    __nv_bfloat16 *xh, *xl, *wqh, *wql, *woh, *wol, *ath, *atl;
    cudaGetSymbolAddress((void**)&qkv, g_qkv);
    cudaGetSymbolAddress((void**)&xh,  g_xh);
    cudaGetSymbolAddress((void**)&xl,  g_xl);
    cudaGetSymbolAddress((void**)&wqh, g_wqh);
    cudaGetSymbolAddress((void**)&wql, g_wql);
    cudaGetSymbolAddress((void**)&woh, g_woh);
    cudaGetSymbolAddress((void**)&wol, g_wol);
    cudaGetSymbolAddress((void**)&ath, g_ath);
    cudaGetSymbolAddress((void**)&atl, g_atl);

    cudaFuncSetAttribute(gemm_tc, cudaFuncAttributeMaxDynamicSharedMemorySize,
                         GEMM_DYN_SMEM);
    cudaFuncSetAttribute(attn_kernel, cudaFuncAttributeMaxDynamicSharedMemorySize,
                         ATTN_SMEM);

    // 0) prep: trig table, x split, weight transpose+split
    trig_kernel<<<32, 256>>>();
    {
        int n4 = (M1 * DIM) / 4;
        split_kernel<<<(n4 + 255) / 256, 256>>>(x, xh, xl, n4);
        dim3 tb(32, 8);
        tsplit_kernel<<<dim3(QKVC / 32, DIM / 32), tb>>>(Wqkv, wqh, wql, DIM, QKVC);
        tsplit_kernel<<<dim3(DIM  / 32, DIM / 32), tb>>>(Wout, woh, wol, DIM, DIM);
    }
    // 1) QKV projection
    gemm_tc<<<dim3(QKVC / 128, M1 / 128), GK_THREADS, GEMM_DYN_SMEM>>>(
        DIM, QKVC, xh, xl, wqh, wql, qkv);
    // 2) fused RoPE + MMA local attention
    attn_kernel<<<B_ * H_ * NW, 256, ATTN_SMEM>>>();
    // 3) output projection
    gemm_tc<<<dim3(DIM / 128, M1 / 128), GK_THREADS, GEMM_DYN_SMEM>>>(
        DIM, DIM, ath, atl, woh, wol, out);
}

// round 16
// speedup vs baseline: 12.4575x; 2.1984x over previous
#include <cuda_runtime.h>
#include <cuda_bf16.h>
#include <cuda_fp16.h>
#include <math.h>
#include <float.h>
#include <stdint.h>

// ---------------------------------------------------------------------------
// Problem constants
// ---------------------------------------------------------------------------
#define B_    4
#define NSEQ  4096
#define DIM   1024
#define H_    16
#define DH    64
#define WS    128
#define NW    32          // NSEQ / WS
#define QKVC  3072
#define M1    (B_ * NSEQ) // 16384
#define BH    (B_ * H_)   // 64

// ---------------------------------------------------------------------------
// Scratch (no cudaMalloc allowed)
// ---------------------------------------------------------------------------
__device__ float  g_qkv [(size_t)M1 * QKVC];   // fp32 qkv (GEMM1 out)
__device__ __half g_xf  [(size_t)M1 * DIM];    // x fp16
__device__ __half g_wqf [(size_t)QKVC * DIM];  // Wqkv^T fp16 [3072][1024]
__device__ __half g_wof [(size_t)DIM * DIM];   // Wout^T fp16 [1024][1024]
__device__ __half g_atf [(size_t)M1 * DIM];    // attention out fp16
__device__ float  g_cs  [256 * 32 * 2];        // [pos][m][cos,sin]

// ---------------------------------------------------------------------------
// PTX helpers (sm_80-era; valid on base sm_103 target)
// ---------------------------------------------------------------------------
__device__ __forceinline__ uint32_t smem_to_u32(const void* p) {
    uint32_t a;
    asm("{ .reg .u64 t; cvta.to.shared.u64 t, %1; cvt.u32.u64 %0, t; }"
        : "=r"(a) : "l"(p));
    return a;
}
__device__ __forceinline__ void ldsm_x4(uint32_t& r0, uint32_t& r1,
                                        uint32_t& r2, uint32_t& r3, uint32_t a) {
    asm volatile("ldmatrix.sync.aligned.m8n8.x4.shared.b16 {%0,%1,%2,%3}, [%4];"
        : "=r"(r0), "=r"(r1), "=r"(r2), "=r"(r3) : "r"(a));
}
__device__ __forceinline__ void ldsm_x4t(uint32_t& r0, uint32_t& r1,
                                         uint32_t& r2, uint32_t& r3, uint32_t a) {
    asm volatile("ldmatrix.sync.aligned.m8n8.x4.trans.shared.b16 {%0,%1,%2,%3}, [%4];"
        : "=r"(r0), "=r"(r1), "=r"(r2), "=r"(r3) : "r"(a));
}
// bf16 mma (attention)
__device__ __forceinline__ void mma_bf16(float* d, const uint32_t* a,
                                         uint32_t b0, uint32_t b1) {
    asm volatile(
        "mma.sync.aligned.m16n8k16.row.col.f32.bf16.bf16.f32 "
        "{%0,%1,%2,%3}, {%4,%5,%6,%7}, {%8,%9}, {%0,%1,%2,%3};"
        : "+f"(d[0]), "+f"(d[1]), "+f"(d[2]), "+f"(d[3])
        : "r"(a[0]), "r"(a[1]), "r"(a[2]), "r"(a[3]), "r"(b0), "r"(b1));
}
// fp16 mma (projection GEMMs)
__device__ __forceinline__ void mma_fp16(float* d, const uint32_t* a,
                                         uint32_t b0, uint32_t b1) {
    asm volatile(
        "mma.sync.aligned.m16n8k16.row.col.f32.f16.f16.f32 "
        "{%0,%1,%2,%3}, {%4,%5,%6,%7}, {%8,%9}, {%0,%1,%2,%3};"
        : "+f"(d[0]), "+f"(d[1]), "+f"(d[2]), "+f"(d[3])
        : "r"(a[0]), "r"(a[1]), "r"(a[2]), "r"(a[3]), "r"(b0), "r"(b1));
}
__device__ __forceinline__ void cp_async16(uint32_t dst, const void* src) {
    asm volatile("cp.async.cg.shared.global [%0], [%1], 16;" :: "r"(dst), "l"(src));
}
#define CP_COMMIT() asm volatile("cp.async.commit_group;" ::: "memory")
#define CP_WAIT(n)  asm volatile("cp.async.wait_group %0;" :: "n"(n) : "memory")

__device__ __forceinline__ uint32_t pack_bf16(float a, float b) {
    __nv_bfloat162 t = __floats2bfloat162_rn(a, b);
    return *(uint32_t*)&t;
}

// ---------------------------------------------------------------------------
// Prep: fp32 -> fp16 convert; transposed fp16 convert for weights; trig table
// ---------------------------------------------------------------------------
__global__ __launch_bounds__(256) void conv_kernel(
    const float* __restrict__ src, __half* __restrict__ dst, int n4)
{
    int i = blockIdx.x * blockDim.x + threadIdx.x;
    if (i >= n4) return;
    float4 v = ((const float4*)src)[i];
    ((__half2*)dst)[i * 2]     = __floats2half2_rn(v.x, v.y);
    ((__half2*)dst)[i * 2 + 1] = __floats2half2_rn(v.z, v.w);
}

// T[n][k] = (half)W[k][n]. W is [K][N] row-major.
__global__ __launch_bounds__(256) void tconv_kernel(
    const float* __restrict__ W, __half* __restrict__ T, int K, int N)
{
    __shared__ float t[32][33];
    int x0 = blockIdx.x * 32, y0 = blockIdx.y * 32;
    int tx = threadIdx.x, ty = threadIdx.y;
    #pragma unroll
    for (int r = ty; r < 32; r += 8)
        t[r][tx] = W[(size_t)(y0 + r) * N + x0 + tx];
    __syncthreads();
    #pragma unroll
    for (int r = ty; r < 32; r += 8)
        T[(size_t)(x0 + r) * K + y0 + tx] = __float2half(t[tx][r]);
}

__global__ __launch_bounds__(256) void trig_kernel()
{
    int t = blockIdx.x * 256 + threadIdx.x; // 0..8191
    int pos = t >> 5, m = t & 31;
    const float RC = 0.28782313662425575f;  // ln(10000)/32
    float f = (float)pos * __expf(-(float)m * RC);
    float s, c;
    __sincosf(f, &s, &c);
    g_cs[(pos * 32 + m) * 2]     = c;
    g_cs[(pos * 32 + m) * 2 + 1] = s;
}

// ---------------------------------------------------------------------------
// fp16 single-term HMMA GEMM: C[M,N] = A[M,K] * B^T (B stored [N][K]).
// CTA tile 128x128, BK=64, 3-stage cp.async pipeline, 8 warps (2x4),
// warp tile 64x32. smem row = 64 fp16 = 128 B; swizzle chunk c ^= (r & 7).
// ---------------------------------------------------------------------------
#define GK_THREADS 256
#define BKC        64
#define STAGES     3
#define TILE_B     16384                 // 128 rows x 128 bytes
#define STAGE_B    (2 * TILE_B)          // A, B
#define GEMM_DYN_SMEM (STAGES * STAGE_B) // 96 KB

__global__ __launch_bounds__(GK_THREADS, 2)
void gemm_tc(int K, int N,
             const __half* __restrict__ A, const __half* __restrict__ B,
             float* __restrict__ C)
{
    extern __shared__ __align__(1024) char smem[];
    const uint32_t smemu = smem_to_u32(smem);

    const int tid  = threadIdx.x;
    const int lane = tid & 31;
    const int wid  = tid >> 5;
    const int wm   = wid & 1;
    const int wn   = wid >> 1;
    const int rowBase = blockIdx.y * 128;
    const int colBase = blockIdx.x * 128;
    const int NCH = K / BKC;

    // 2048 x 16B chunks per stage / 256 threads = 8 per thread
    const __half* srcp[8];
    uint32_t dsto[8];
    {
        const __half* bases[2] = { A + (size_t)rowBase * K,
                                   B + (size_t)colBase * K };
        #pragma unroll
        for (int i = 0; i < 8; ++i) {
            int g = i * GK_THREADS + tid;
            int tile = g >> 10, idx = g & 1023, r = idx >> 3, c = idx & 7;
            srcp[i] = bases[tile] + (size_t)r * K + c * 8;
            dsto[i] = tile * TILE_B + r * 128 + ((c ^ (r & 7)) << 4);
        }
    }
    auto load_stage = [&](int st) {
        const uint32_t sb = smemu + st * STAGE_B;
        #pragma unroll
        for (int i = 0; i < 8; ++i) { cp_async16(sb + dsto[i], srcp[i]); srcp[i] += BKC; }
    };

    float acc[4][4][4];
    #pragma unroll
    for (int a = 0; a < 4; ++a)
        #pragma unroll
        for (int b = 0; b < 4; ++b)
            #pragma unroll
            for (int d = 0; d < 4; ++d) acc[a][b][d] = 0.0f;

    #pragma unroll
    for (int s = 0; s < STAGES - 1; ++s) { load_stage(s); CP_COMMIT(); }

    const int rA = lane & 15;
    const int kq = lane >> 4;   // 0/1: which 16B chunk within the k16 slab

    for (int c = 0; c < NCH; ++c) {
        CP_WAIT(STAGES - 2);
        __syncthreads();
        if (c + STAGES - 1 < NCH) load_stage((c + STAGES - 1) % STAGES);
        CP_COMMIT();

        const uint32_t stA = smemu + (c % STAGES) * STAGE_B;
        const uint32_t stB = stA + TILE_B;

        #pragma unroll
        for (int ks = 0; ks < 4; ++ks) {   // 4 k16 slabs in BKC=64
            uint32_t af[4][4], bf[2][4];
            #pragma unroll
            for (int mt = 0; mt < 4; ++mt) {
                int row = wm * 64 + mt * 16 + rA;
                uint32_t addr = stA + row * 128 + (((2 * ks + kq) ^ (row & 7)) << 4);
                ldsm_x4(af[mt][0], af[mt][1], af[mt][2], af[mt][3], addr);
            }
            #pragma unroll
            for (int t = 0; t < 2; ++t) {
                int row = wn * 32 + t * 16 + rA;
                uint32_t addr = stB + row * 128 + (((2 * ks + kq) ^ (row & 7)) << 4);
                ldsm_x4(bf[t][0], bf[t][1], bf[t][2], bf[t][3], addr);
            }
            #pragma unroll
            for (int mt = 0; mt < 4; ++mt)
                #pragma unroll
                for (int t = 0; t < 2; ++t) {
                    mma_fp16(acc[mt][2*t],   af[mt], bf[t][0], bf[t][2]);
                    mma_fp16(acc[mt][2*t+1], af[mt], bf[t][1], bf[t][3]);
                }
        }
    }

    #pragma unroll
    for (int mt = 0; mt < 4; ++mt) {
        int row0 = rowBase + wm * 64 + mt * 16 + (lane >> 2);
        #pragma unroll
        for (int nt = 0; nt < 4; ++nt) {
            int col = colBase + wn * 32 + nt * 8 + (lane & 3) * 2;
            *(float2*)&C[(size_t)row0 * N + col] = make_float2(acc[mt][nt][0], acc[mt][nt][1]);
            *(float2*)&C[(size_t)(row0+8) * N + col] = make_float2(acc[mt][nt][2], acc[mt][nt][3]);
        }
    }
}

// ---------------------------------------------------------------------------
// MMA flash-style local attention with FUSED RoPE + bf16 split (unchanged
// internals); output now a single fp16 array for the fp16 GEMM2.
// ---------------------------------------------------------------------------
#define SQH 0
#define SQL 16384
#define SKH 32768
#define SKL 65536
#define SVH 98304
#define SVL 131072
#define ATTN_SMEM 163840

__global__ __launch_bounds__(256) void attn_kernel()
{
    extern __shared__ __align__(1024) char asm_[];
    const uint32_t sb = smem_to_u32(asm_);

    const int blk = blockIdx.x;
    const int w = blk & (NW - 1);
    const int h = (blk >> 5) & (H_ - 1);
    const int b = blk >> 9;
    const int tid  = threadIdx.x;
    const int lane = tid & 31;
    const int wr   = tid >> 5;

    // ---- fused load + RoPE + split: 640 rows (Q128, K256, V256) ----------
    {
        const int grp = tid >> 3;
        const int qd  = tid & 7;
        #pragma unroll
        for (int it = 0; it < 20; ++it) {
            int rid = it * 32 + grp;
            int kind = (rid < 128) ? 0 : (rid < 384 ? 1 : 2);
            int r = rid - ((kind == 0) ? 0 : (kind == 1 ? 128 : 384));
            int n, pos;
            uint32_t dH, dL;
            if (kind == 0) { n = w * WS + r;  pos = 128 + r; dH = SQH; dL = SQL; }
            else {
                n = (w == 0) ? r % WS : (w - 1) * WS + r;
                pos = r;
                dH = (kind == 1) ? SKH : SVH;
                dL = (kind == 1) ? SKL : SVL;
            }
            const float* src = &g_qkv[(size_t)(b * NSEQ + n) * QKVC
                                      + kind * DIM + h * DH];
            float4 a  = *(const float4*)(src + qd * 4);
            float4 bq = *(const float4*)(src + 32 + qd * 4);
            float o0[4], o1[4];
            if (kind < 2) {
                const float4 cs0 = *(const float4*)&g_cs[(pos * 32 + qd * 4) * 2];
                const float4 cs1 = *(const float4*)&g_cs[(pos * 32 + qd * 4) * 2 + 4];
                float sc = (kind == 0) ? 0.125f : 1.0f;
                o0[0] = (a.x * cs0.x - bq.x * cs0.y) * sc;
                o1[0] = (bq.x * cs0.x + a.x * cs0.y) * sc;
                o0[1] = (a.y * cs0.z - bq.y * cs0.w) * sc;
                o1[1] = (bq.y * cs0.z + a.y * cs0.w) * sc;
                o0[2] = (a.z * cs1.x - bq.z * cs1.y) * sc;
                o1[2] = (bq.z * cs1.x + a.z * cs1.y) * sc;
                o0[3] = (a.w * cs1.z - bq.w * cs1.w) * sc;
                o1[3] = (bq.w * cs1.z + a.w * cs1.w) * sc;
            } else {
                o0[0] = a.x;  o0[1] = a.y;  o0[2] = a.z;  o0[3] = a.w;
                o1[0] = bq.x; o1[1] = bq.y; o1[2] = bq.z; o1[3] = bq.w;
            }
            uint32_t offL = r * 128 + ((((qd >> 1))     ^ (r & 7)) << 4) + (qd & 1) * 8;
            uint32_t offH = r * 128 + (((4 + (qd >> 1)) ^ (r & 7)) << 4) + (qd & 1) * 8;
            uint32_t h0 = pack_bf16(o0[0], o0[1]);
            uint32_t h1 = pack_bf16(o0[2], o0[3]);
            uint32_t h2 = pack_bf16(o1[0], o1[1]);
            uint32_t h3 = pack_bf16(o1[2], o1[3]);
            *(uint2*)(asm_ + dH + offL) = make_uint2(h0, h1);
            *(uint2*)(asm_ + dH + offH) = make_uint2(h2, h3);
            __nv_bfloat162* p0 = (__nv_bfloat162*)&h0;
            __nv_bfloat162* p1 = (__nv_bfloat162*)&h1;
            __nv_bfloat162* p2 = (__nv_bfloat162*)&h2;
            __nv_bfloat162* p3 = (__nv_bfloat162*)&h3;
            uint32_t l0 = pack_bf16(o0[0] - __bfloat162float(__low2bfloat16(*p0)),
                                    o0[1] - __bfloat162float(__high2bfloat16(*p0)));
            uint32_t l1 = pack_bf16(o0[2] - __bfloat162float(__low2bfloat16(*p1)),
                                    o0[3] - __bfloat162float(__high2bfloat16(*p1)));
            uint32_t l2 = pack_bf16(o1[0] - __bfloat162float(__low2bfloat16(*p2)),
                                    o1[1] - __bfloat162float(__high2bfloat16(*p2)));
            uint32_t l3 = pack_bf16(o1[2] - __bfloat162float(__low2bfloat16(*p3)),
                                    o1[3] - __bfloat162float(__high2bfloat16(*p3)));
            *(uint2*)(asm_ + dL + offL) = make_uint2(l0, l1);
            *(uint2*)(asm_ + dL + offH) = make_uint2(l2, l3);
        }
    }
    __syncthreads();

    const int row0 = 16 * wr;
    const int nb0  = (w == 0) ? 8 : wr;
    const int NB   = (w == 0) ? wr + 1 : 9;

    // ---- S = Q K^T, band only --------------------------------------------
    float sacc[9][8];
    #pragma unroll
    for (int i = 0; i < 9; ++i)
        #pragma unroll
        for (int j = 0; j < 8; ++j) sacc[i][j] = 0.0f;

    #pragma unroll
    for (int ks = 0; ks < 4; ++ks) {
        uint32_t aqh[4], aql[4];
        {
            int r = row0 + (lane & 15);
            int ch = 2 * ks + (lane >> 4);
            uint32_t off = r * 128 + ((ch ^ (r & 7)) << 4);
            ldsm_x4(aqh[0], aqh[1], aqh[2], aqh[3], sb + SQH + off);
            ldsm_x4(aql[0], aql[1], aql[2], aql[3], sb + SQL + off);
        }
        #pragma unroll
        for (int nb = 0; nb < 9; ++nb) {
            if (nb >= NB) break;
            int kb = nb0 + nb;
            uint32_t bh[4], bl[4];
            int r = kb * 16 + (lane & 15);
            int ch = 2 * ks + (lane >> 4);
            uint32_t off = r * 128 + ((ch ^ (r & 7)) << 4);
            ldsm_x4(bh[0], bh[1], bh[2], bh[3], sb + SKH + off);
            ldsm_x4(bl[0], bl[1], bl[2], bl[3], sb + SKL + off);
            mma_bf16(sacc[nb],     aqh, bh[0], bh[2]);
            mma_bf16(sacc[nb],     aqh, bl[0], bl[2]);
            mma_bf16(sacc[nb],     aql, bh[0], bh[2]);
            mma_bf16(sacc[nb] + 4, aqh, bh[1], bh[3]);
            mma_bf16(sacc[nb] + 4, aqh, bl[1], bl[3]);
            mma_bf16(sacc[nb] + 4, aql, bh[1], bh[3]);
        }
    }

    // ---- masked softmax in registers --------------------------------------
    const int g  = lane >> 2;
    const int tq = lane & 3;
    const int i0 = row0 + g;
    const int i1 = i0 + 8;
    const int jlo0 = (w == 0) ? (i0 < 128 ? 128 : i0) : i0;
    const int jlo1 = (w == 0) ? (i1 < 128 ? 128 : i1) : i1;

    float mx0 = -FLT_MAX, mx1 = -FLT_MAX;
    #pragma unroll
    for (int nb = 0; nb < 9; ++nb) {
        if (nb >= NB) break;
        int cb = 16 * (nb0 + nb) + 2 * tq;
        #pragma unroll
        for (int t2 = 0; t2 < 2; ++t2)
            #pragma unroll
            for (int d = 0; d < 2; ++d) {
                int c = cb + 8 * t2 + d;
                if (c >= jlo0 && c <= i0 + 128) mx0 = fmaxf(mx0, sacc[nb][t2*4 + d]);
                if (c >= jlo1 && c <= i1 + 128) mx1 = fmaxf(mx1, sacc[nb][t2*4 + 2 + d]);
            }
    }
    mx0 = fmaxf(mx0, __shfl_xor_sync(0xffffffffu, mx0, 1));
    mx0 = fmaxf(mx0, __shfl_xor_sync(0xffffffffu, mx0, 2));
    mx1 = fmaxf(mx1, __shfl_xor_sync(0xffffffffu, mx1, 1));
    mx1 = fmaxf(mx1, __shfl_xor_sync(0xffffffffu, mx1, 2));

    float sum0 = 0.f, sum1 = 0.f;
    #pragma unroll
    for (int nb = 0; nb < 9; ++nb) {
        if (nb >= NB) break;
        int cb = 16 * (nb0 + nb) + 2 * tq;
        #pragma unroll
        for (int t2 = 0; t2 < 2; ++t2)
            #pragma unroll
            for (int d = 0; d < 2; ++d) {
                int c = cb + 8 * t2 + d;
                float e0 = (c >= jlo0 && c <= i0 + 128)
                         ? __expf(sacc[nb][t2*4 + d] - mx0) : 0.f;
                float e1 = (c >= jlo1 && c <= i1 + 128)
                         ? __expf(sacc[nb][t2*4 + 2 + d] - mx1) : 0.f;
                sacc[nb][t2*4 + d]     = e0;  sum0 += e0;
                sacc[nb][t2*4 + 2 + d] = e1;  sum1 += e1;
            }
    }
    sum0 += __shfl_xor_sync(0xffffffffu, sum0, 1);
    sum0 += __shfl_xor_sync(0xffffffffu, sum0, 2);
    sum1 += __shfl_xor_sync(0xffffffffu, sum1, 1);
    sum1 += __shfl_xor_sync(0xffffffffu, sum1, 2);
    const float inv0 = 1.0f / sum0;
    const float inv1 = 1.0f / sum1;

    // ---- O = P V -----------------------------------------------------------
    float oacc[8][4];
    #pragma unroll
    for (int i = 0; i < 8; ++i)
        #pragma unroll
        for (int j = 0; j < 4; ++j) oacc[i][j] = 0.0f;

    #pragma unroll
    for (int nb = 0; nb < 9; ++nb) {
        if (nb >= NB) break;
        int kb = nb0 + nb;
        uint32_t ph[4], pl[4];
        #pragma unroll
        for (int q = 0; q < 4; ++q) {
            float v0 = sacc[nb][q * 2], v1 = sacc[nb][q * 2 + 1];
            __nv_bfloat162 hi2 = __floats2bfloat162_rn(v0, v1);
            ph[q] = *(uint32_t*)&hi2;
            pl[q] = pack_bf16(v0 - __bfloat162float(__low2bfloat16(hi2)),
                              v1 - __bfloat162float(__high2bfloat16(hi2)));
        }
        #pragma unroll
        for (int dg = 0; dg < 4; ++dg) {
            int rrow = kb * 16 + (lane & 7) + ((lane >> 3) & 1) * 8;
            int ch   = 2 * dg + (lane >> 4);
            uint32_t off = rrow * 128 + ((ch ^ (rrow & 7)) << 4);
            uint32_t vh[4], vl[4];
            ldsm_x4t(vh[0], vh[1], vh[2], vh[3], sb + SVH + off);
            ldsm_x4t(vl[0], vl[1], vl[2], vl[3], sb + SVL + off);
            mma_bf16(oacc[2*dg],   ph, vh[0], vh[1]);
            mma_bf16(oacc[2*dg],   ph, vl[0], vl[1]);
            mma_bf16(oacc[2*dg],   pl, vh[0], vh[1]);
            mma_bf16(oacc[2*dg+1], ph, vh[2], vh[3]);
            mma_bf16(oacc[2*dg+1], ph, vl[2], vl[3]);
            mma_bf16(oacc[2*dg+1], pl, vh[2], vh[3]);
        }
    }

    // ---- write fp16 output for fp16 GEMM2 ----------------------------------
    const size_t ro0 = ((size_t)b * NSEQ + w * WS + i0) * DIM + h * DH;
    const size_t ro1 = ((size_t)b * NSEQ + w * WS + i1) * DIM + h * DH;
    #pragma unroll
    for (int nt = 0; nt < 8; ++nt) {
        int c0 = 8 * nt + 2 * tq;
        *(__half2*)&g_atf[ro0 + c0] =
            __floats2half2_rn(oacc[nt][0] * inv0, oacc[nt][1] * inv0);
        *(__half2*)&g_atf[ro1 + c0] =
            __floats2half2_rn(oacc[nt][2] * inv1, oacc[nt][3] * inv1);
    }
}

// ---------------------------------------------------------------------------
extern "C" void kernel_launch(void* const* d_in, const int* in_sizes, int n_in,
                              void* d_out, int out_size)
{
    const float* x    = (const float*)d_in[0];
    const float* Wqkv = (const float*)d_in[1];
    const float* Wout = (const float*)d_in[2];
    float* out = (float*)d_out;

    float *qkv;
    __half *xf, *wqf, *wof, *atf;
    cudaGetSymbolAddress((void**)&qkv, g_qkv);
    cudaGetSymbolAddress((void**)&xf,  g_xf);
    cudaGetSymbolAddress((void**)&wqf, g_wqf);
    cudaGetSymbolAddress((void**)&wof, g_wof);
    cudaGetSymbolAddress((void**)&atf, g_atf);

    cudaFuncSetAttribute(gemm_tc, cudaFuncAttributeMaxDynamicSharedMemorySize,
                         GEMM_DYN_SMEM);
    cudaFuncSetAttribute(attn_kernel, cudaFuncAttributeMaxDynamicSharedMemorySize,
                         ATTN_SMEM);

    // 0) prep: trig table, x convert, weight transpose+convert
    trig_kernel<<<32, 256>>>();
    {
        int n4 = (M1 * DIM) / 4;
        conv_kernel<<<(n4 + 255) / 256, 256>>>(x, xf, n4);
        dim3 tb(32, 8);
        tconv_kernel<<<dim3(QKVC / 32, DIM / 32), tb>>>(Wqkv, wqf, DIM, QKVC);
        tconv_kernel<<<dim3(DIM  / 32, DIM / 32), tb>>>(Wout, wof, DIM, DIM);
    }
    // 1) QKV projection (fp16 single-term)
    gemm_tc<<<dim3(QKVC / 128, M1 / 128), GK_THREADS, GEMM_DYN_SMEM>>>(
        DIM, QKVC, xf, wqf, qkv);
    // 2) fused RoPE + MMA local attention
    attn_kernel<<<B_ * H_ * NW, 256, ATTN_SMEM>>>();
    // 3) output projection (fp16 single-term)
    gemm_tc<<<dim3(DIM / 128, M1 / 128), GK_THREADS, GEMM_DYN_SMEM>>>(
        DIM, DIM, atf, wof, out);
}